// round 8
// baseline (speedup 1.0000x reference)
#include <cuda_runtime.h>
#include <cuda_fp16.h>
#include <math.h>
#include <stdint.h>

// ---------------- model dims ----------------
#define BATCH      2
#define SEQ        1024
#define M_ROWS     (BATCH*SEQ)        // 2048
#define D_MODEL    768
#define D_INNER    1536
#define D_STATE    16
#define DT_RANK    48
#define D_CONV     4
#define XDBL_COLS  (DT_RANK + 2*D_STATE)   // 80
#define VOCAB      32000
#define N_LAYER    2
#define EPS        1e-5f

// ---------------- fp32 scratch ----------------
__device__ __align__(16) float g_x    [M_ROWS * D_MODEL];
__device__ __align__(16) float g_xr   [M_ROWS * 2 * D_INNER];
__device__ __align__(16) float g_u    [M_ROWS * D_INNER];
__device__ __align__(16) float g_xdbl [M_ROWS * XDBL_COLS];
__device__ __align__(16) float g_delta[M_ROWS * D_INNER];
__device__ __align__(16) float g_part [4 * M_ROWS * D_MODEL];

// ---------------- fp16 hi/lo split buffers ----------------
__device__ __align__(16) __half g_emb_h [VOCAB*D_MODEL];
__device__ __align__(16) __half g_emb_l [VOCAB*D_MODEL];
__device__ __align__(16) __half g_inpw_h[N_LAYER*2*D_INNER*D_MODEL];
__device__ __align__(16) __half g_inpw_l[N_LAYER*2*D_INNER*D_MODEL];
__device__ __align__(16) __half g_outpw_h[N_LAYER*D_MODEL*D_INNER];
__device__ __align__(16) __half g_outpw_l[N_LAYER*D_MODEL*D_INNER];
__device__ __align__(16) __half g_xn_h[M_ROWS*D_MODEL];
__device__ __align__(16) __half g_xn_l[M_ROWS*D_MODEL];
__device__ __align__(16) __half g_u_h [M_ROWS*D_INNER];
__device__ __align__(16) __half g_u_l [M_ROWS*D_INNER];
__device__ __align__(16) __half g_y_h [M_ROWS*D_INNER];
__device__ __align__(16) __half g_y_l [M_ROWS*D_INNER];
__device__ __align__(16) __half g_xpw_h[128*D_INNER];
__device__ __align__(16) __half g_xpw_l[128*D_INNER];
__device__ __align__(16) __half g_dtw_h[D_INNER*64];
__device__ __align__(16) __half g_dtw_l[D_INNER*64];
__device__ __align__(16) __half g_xdp_h[M_ROWS*64];
__device__ __align__(16) __half g_xdp_l[M_ROWS*64];

// ================= helpers =================
__device__ __forceinline__ void split2(float v, __half& h, __half& l) {
    h = __float2half_rn(v);
    l = __float2half_rn(v - __half2float(h));
}

// ================= small kernels =================
__global__ void embed_kernel(const int* __restrict__ ids,
                             const float* __restrict__ emb,
                             float* __restrict__ x)
{
    int row = blockIdx.x;
    int tok = ids[row];
    const float4* src = (const float4*)(emb + (long)tok * D_MODEL);
    float4* dst = (float4*)(x + (long)row * D_MODEL);
    for (int i = threadIdx.x; i < D_MODEL/4; i += blockDim.x) dst[i] = src[i];
}

__global__ void rmsnorm_split_kernel(const float* __restrict__ x,
                                     const float* __restrict__ w,
                                     __half* __restrict__ oh,
                                     __half* __restrict__ ol)
{
    __shared__ float red[8];
    int row = blockIdx.x;
    const float* xp = x + (long)row * D_MODEL;
    float s = 0.f;
    for (int i = threadIdx.x; i < D_MODEL; i += 256) { float v = xp[i]; s += v*v; }
    #pragma unroll
    for (int o = 16; o; o >>= 1) s += __shfl_xor_sync(0xffffffffu, s, o);
    if ((threadIdx.x & 31) == 0) red[threadIdx.x >> 5] = s;
    __syncthreads();
    if (threadIdx.x < 8) {
        float t = red[threadIdx.x];
        #pragma unroll
        for (int o = 4; o; o >>= 1) t += __shfl_xor_sync(0xffu, t, o);
        if (threadIdx.x == 0) red[0] = t;
    }
    __syncthreads();
    float scale = rsqrtf(red[0] / (float)D_MODEL + EPS);
    for (int i = threadIdx.x; i < D_MODEL; i += 256) {
        float v = xp[i] * scale * w[i];
        __half h, l; split2(v, h, l);
        oh[(long)row * D_MODEL + i] = h;
        ol[(long)row * D_MODEL + i] = l;
    }
}

__global__ void split4_kernel(const float4* __restrict__ s, int n4,
                              __half2* __restrict__ h, __half2* __restrict__ l)
{
    int i = blockIdx.x * blockDim.x + threadIdx.x;
    if (i >= n4) return;
    float4 v = s[i];
    __half hx,lx,hy,ly,hz,lz,hw,lw;
    split2(v.x,hx,lx); split2(v.y,hy,ly); split2(v.z,hz,lz); split2(v.w,hw,lw);
    h[2*i]   = __halves2half2(hx,hy);
    h[2*i+1] = __halves2half2(hz,hw);
    l[2*i]   = __halves2half2(lx,ly);
    l[2*i+1] = __halves2half2(lz,lw);
}

__global__ void split_pad_rows4(const float* __restrict__ s, int rows_real, int K,
                                int rows_pad,
                                __half2* __restrict__ h, __half2* __restrict__ l)
{
    int i = blockIdx.x * blockDim.x + threadIdx.x;
    int n4 = rows_pad * K / 4;
    if (i >= n4) return;
    int r = (i*4) / K;
    float4 v = (r < rows_real) ? *(const float4*)(s + (long)(i*4))
                               : make_float4(0,0,0,0);
    __half hx,lx,hy,ly,hz,lz,hw,lw;
    split2(v.x,hx,lx); split2(v.y,hy,ly); split2(v.z,hz,lz); split2(v.w,hw,lw);
    h[2*i]   = __halves2half2(hx,hy);
    h[2*i+1] = __halves2half2(hz,hw);
    l[2*i]   = __halves2half2(lx,ly);
    l[2*i+1] = __halves2half2(lz,lw);
}

__global__ void split_pad_cols4(const float* __restrict__ s, int rows, int src_ld,
                                int k_take, int k_pad,
                                __half2* __restrict__ h, __half2* __restrict__ l)
{
    int i = blockIdx.x * blockDim.x + threadIdx.x;
    int n4 = rows * k_pad / 4;
    if (i >= n4) return;
    int kp4 = k_pad / 4;
    int r = i / kp4, k = (i % kp4) * 4;
    float4 v = (k < k_take) ? *(const float4*)(s + (long)r * src_ld + k)
                            : make_float4(0,0,0,0);
    __half hx,lx,hy,ly,hz,lz,hw,lw;
    split2(v.x,hx,lx); split2(v.y,hy,ly); split2(v.z,hz,lz); split2(v.w,hw,lw);
    h[2*i]   = __halves2half2(hx,hy);
    h[2*i+1] = __halves2half2(hz,hw);
    l[2*i]   = __halves2half2(lx,ly);
    l[2*i+1] = __halves2half2(lz,lw);
}

__global__ void conv_silu_split_kernel(const float* __restrict__ xr,
                                       const float* __restrict__ cw,
                                       const float* __restrict__ cb,
                                       float* __restrict__ u,
                                       __half2* __restrict__ uh,
                                       __half2* __restrict__ ul)
{
    int i = blockIdx.x * blockDim.x + threadIdx.x;
    if (i >= M_ROWS * D_INNER / 4) return;
    int c = (i*4) % D_INNER;
    int m = (i*4) / D_INNER;
    int l = m % SEQ;
    const float* base = xr + (long)m * (2*D_INNER) + c;
    float4 v0  = *(const float4*)base;
    float4 vm1 = (l >= 1) ? *(const float4*)(base - 1*(2*D_INNER)) : make_float4(0,0,0,0);
    float4 vm2 = (l >= 2) ? *(const float4*)(base - 2*(2*D_INNER)) : make_float4(0,0,0,0);
    float4 vm3 = (l >= 3) ? *(const float4*)(base - 3*(2*D_INNER)) : make_float4(0,0,0,0);
    float4 cbv = *(const float4*)(cb + c);
    const float* p0 = &v0.x; const float* p1 = &vm1.x;
    const float* p2 = &vm2.x; const float* p3 = &vm3.x;
    const float* pb = &cbv.x;
    float o[4];
    #pragma unroll
    for (int t = 0; t < 4; t++) {
        float4 w = *(const float4*)(cw + (c + t) * 4);
        float acc = pb[t] + w.w * p0[t] + w.z * p1[t] + w.y * p2[t] + w.x * p3[t];
        o[t] = acc / (1.f + __expf(-acc));
    }
    *(float4*)(u + (long)i*4) = make_float4(o[0], o[1], o[2], o[3]);
    __half hx,lx,hy,ly,hz,lz,hw,lw;
    split2(o[0],hx,lx); split2(o[1],hy,ly); split2(o[2],hz,lz); split2(o[3],hw,lw);
    uh[2*i]   = __halves2half2(hx,hy);
    uh[2*i+1] = __halves2half2(hz,hw);
    ul[2*i]   = __halves2half2(lx,ly);
    ul[2*i+1] = __halves2half2(lz,lw);
}

__global__ void reduce_xp_kernel(const float* __restrict__ p,
                                 float* __restrict__ xdbl,
                                 __half* __restrict__ xdph,
                                 __half* __restrict__ xdpl)
{
    int i = blockIdx.x * blockDim.x + threadIdx.x;
    if (i >= M_ROWS * 128) return;
    int r = i >> 7, c = i & 127;
    const long S = (long)M_ROWS * 128;
    float s = 0.f;
    #pragma unroll
    for (int z = 0; z < 8; z++) s += p[z*S + i];
    if (c < XDBL_COLS) xdbl[(long)r * XDBL_COLS + c] = s;
    if (c < 64) {
        float v = (c < DT_RANK) ? s : 0.f;
        __half h, l; split2(v, h, l);
        xdph[(long)r*64 + c] = h;
        xdpl[(long)r*64 + c] = l;
    }
}

__global__ void reduce_out_kernel(const float* __restrict__ p,
                                  float* __restrict__ x)
{
    int i = blockIdx.x * blockDim.x + threadIdx.x;
    if (i >= M_ROWS * D_MODEL / 4) return;
    const long S4 = (long)M_ROWS * D_MODEL / 4;
    const float4* p4 = (const float4*)p;
    float4 a = ((float4*)x)[i];
    #pragma unroll
    for (int z = 0; z < 4; z++) {
        float4 b = p4[z*S4 + i];
        a.x += b.x; a.y += b.y; a.z += b.z; a.w += b.w;
    }
    ((float4*)x)[i] = a;
}

// selective scan: software-pipelined loads; D skip + silu gate + fp16 split
__global__ void scan_kernel(const float* __restrict__ delta,
                            const float* __restrict__ u,
                            const float* __restrict__ xdbl,
                            const float* __restrict__ xr,
                            const float* __restrict__ A_log,
                            const float* __restrict__ Dp,
                            __half* __restrict__ yh,
                            __half* __restrict__ yl)
{
    int gid  = blockIdx.x * (blockDim.x / 16) + (threadIdx.x / 16);
    int lane = threadIdx.x & 15;
    if (gid >= BATCH * D_INNER) return;
    int b  = gid / D_INNER;
    int di = gid % D_INNER;

    float An = -__expf(A_log[di * D_STATE + lane]);
    float Dv = Dp[di];
    float h  = 0.f;

    long m0 = (long)b * SEQ;
    const float* dptr = delta + m0 * D_INNER + di;
    const float* uptr = u     + m0 * D_INNER + di;
    const float* rptr = xr    + m0 * (2*D_INNER) + D_INNER + di;
    const float* bptr = xdbl  + m0 * XDBL_COLS + DT_RANK + lane;
    const float* cptr = xdbl  + m0 * XDBL_COLS + DT_RANK + D_STATE + lane;
    __half* yhp = yh + m0 * D_INNER + di;
    __half* ylp = yl + m0 * D_INNER + di;

    float dv = dptr[0], uv = uptr[0], Bv = bptr[0], Cv = cptr[0], rv = rptr[0];

    for (int l = 0; l < SEQ; l++) {
        float dv_n, uv_n, Bv_n, Cv_n, rv_n;
        if (l + 1 < SEQ) {
            long ln = l + 1;
            dv_n = dptr[ln * D_INNER];
            uv_n = uptr[ln * D_INNER];
            Bv_n = bptr[ln * XDBL_COLS];
            Cv_n = cptr[ln * XDBL_COLS];
            rv_n = rptr[ln * (2*D_INNER)];
        } else { dv_n = uv_n = Bv_n = Cv_n = rv_n = 0.f; }

        float dA = __expf(dv * An);
        h = fmaf(dA, h, dv * Bv * uv);
        float p = h * Cv;
        p += __shfl_xor_sync(0xffffffffu, p, 8);
        p += __shfl_xor_sync(0xffffffffu, p, 4);
        p += __shfl_xor_sync(0xffffffffu, p, 2);
        p += __shfl_xor_sync(0xffffffffu, p, 1);
        if (lane == 0) {
            float yv = (p + uv * Dv) * (rv / (1.f + __expf(-rv)));
            __half hb, lb; split2(yv, hb, lb);
            yhp[(long)l * D_INNER] = hb;
            ylp[(long)l * D_INNER] = lb;
        }
        dv = dv_n; uv = uv_n; Bv = Bv_n; Cv = Cv_n; rv = rv_n;
    }
}

// ================= mma.sync split-fp16 GEMM =================
// Template: BM (128 or 256) x 128 x 32 tiles, BM/64 x 4 warps (warp tile 64x32),
// 2-stage cp.async, ldmatrix.x4 A+B.
// TERMS=3: D = Ah*Bh + Ah*Bl + Al*Bh    TERMS=2: D = A*Bh (Bl never loaded)
// mode 0: plain (C += z*zstride)   mode 1: softplus(acc + ext[col])
#define GPITCH 40

__device__ __forceinline__ uint32_t smem_u32(const void* p) {
    uint32_t a;
    asm("{ .reg .u64 t; cvta.to.shared.u64 t, %1; cvt.u32.u64 %0, t; }" : "=r"(a) : "l"(p));
    return a;
}

#define LDSM_X4(r, addr) \
    asm volatile("ldmatrix.sync.aligned.m8n8.x4.shared.b16 {%0,%1,%2,%3}, [%4];" \
        : "=r"((r)[0]),"=r"((r)[1]),"=r"((r)[2]),"=r"((r)[3]) : "r"(addr))

#define MMA_F16(c, a, b) \
    asm volatile("mma.sync.aligned.m16n8k16.row.col.f32.f16.f16.f32 " \
        "{%0,%1,%2,%3},{%4,%5,%6,%7},{%8,%9},{%0,%1,%2,%3};" \
        : "+f"((c)[0]),"+f"((c)[1]),"+f"((c)[2]),"+f"((c)[3]) \
        : "r"((a)[0]),"r"((a)[1]),"r"((a)[2]),"r"((a)[3]),"r"((b)[0]),"r"((b)[1]))

#define CP16(dst, src) \
    asm volatile("cp.async.cg.shared.global [%0], [%1], 16;" :: "r"(dst), "l"(src))
#define CP_COMMIT() asm volatile("cp.async.commit_group;" ::: "memory")
#define CP_WAIT(n)  asm volatile("cp.async.wait_group %0;" :: "n"(n) : "memory")

#define GSMEM(BM) (2 * (2*(BM) + 256) * GPITCH * 2)   // 2 stages

template<int BM, int TERMS>
__global__ void __launch_bounds__(BM*2, (BM==128)?2:1) mma_gemm(
    const __half* __restrict__ Ah, const __half* __restrict__ Al,
    const __half* __restrict__ Bh, const __half* __restrict__ Bl,
    int lda, int klen,
    float* __restrict__ C, int ldc, int Nreal,
    const float* __restrict__ ext, int mode, long zstride)
{
    constexpr int NTHR  = BM * 2;
    constexpr int SELEM = (2*BM + 256) * GPITCH;
    constexpr int LITER = (2*BM + 256) * 4 / NTHR;

    extern __shared__ __half sm[];
    const uint32_t sbase = smem_u32(sm);
    const int tid  = threadIdx.x;
    const int lane = tid & 31;
    const int w    = tid >> 5;
    const int wm   = (w >> 2) << 6;
    const int wn   = (w & 3) << 5;
    const long bm  = (long)blockIdx.y * BM;
    const long bn  = (long)blockIdx.x * 128;
    const int koff = blockIdx.z * klen;
    C += (long)blockIdx.z * zstride;

    float acc[4][4][4];
    #pragma unroll
    for (int i = 0; i < 4; i++)
        #pragma unroll
        for (int j = 0; j < 4; j++)
            #pragma unroll
            for (int e = 0; e < 4; e++) acc[i][j][e] = 0.f;

    const int NC = klen >> 5;

    #define LOAD_STAGE(st, kc) do {                                           \
        int _k0 = koff + ((kc) << 5);                                         \
        _Pragma("unroll")                                                     \
        for (int _it = 0; _it < LITER; _it++) {                               \
            int _i = _it * NTHR + tid;                                        \
            int _rg = _i >> 2, _ch = _i & 3;                                  \
            if (TERMS == 2 && _rg >= 2*BM + 128) continue;   /* skip Bl */    \
            const __half* _gb; long _grow;                                    \
            if (_rg < 2*BM) {                                                 \
                int _a = _rg >= BM;                                           \
                _gb = _a ? Al : Ah; _grow = bm + (_rg - _a * BM);             \
            } else {                                                          \
                int _rb = _rg - 2*BM;                                         \
                int _a = _rb >= 128;                                          \
                _gb = _a ? Bl : Bh; _grow = bn + (_rb - _a * 128);            \
            }                                                                 \
            const void* _src = _gb + _grow * (long)lda + _k0 + _ch * 8;       \
            uint32_t _dst = sbase + ((st) * SELEM + _rg * GPITCH              \
                                     + _ch * 8) * 2;                          \
            CP16(_dst, _src);                                                 \
        }                                                                     \
        CP_COMMIT();                                                          \
    } while (0)

    LOAD_STAGE(0, 0);
    LOAD_STAGE(1, 1);

    for (int c = 0; c < NC; c++) {
        if (c + 1 < NC) CP_WAIT(1);
        else            CP_WAIT(0);
        __syncthreads();

        const int s = c & 1;
        const uint32_t stg = sbase + (s * SELEM) * 2;
        const uint32_t aH = stg;
        const uint32_t aL = stg + (BM * GPITCH) * 2;
        const uint32_t bH = stg + (2 * BM * GPITCH) * 2;
        const uint32_t bL = bH + (128 * GPITCH) * 2;

        #pragma unroll
        for (int ks = 0; ks < 2; ks++) {
            const int k0 = ks << 4;
            const uint32_t aoff = ((wm + (lane & 15)) * GPITCH
                                   + k0 + ((lane >> 4) << 3)) * 2;
            const int brow = wn + (lane & 7) + ((lane >> 4) << 3);
            const uint32_t boff = (brow * GPITCH + k0 + (((lane >> 3) & 1) << 3)) * 2;

            uint32_t ah[4][4], al[4][4];
            uint32_t bhf[2][4];
            #pragma unroll
            for (int mi = 0; mi < 4; mi++)
                LDSM_X4(ah[mi], aH + aoff + mi * 16 * GPITCH * 2);
            LDSM_X4(bhf[0], bH + boff);
            LDSM_X4(bhf[1], bH + boff + 16 * GPITCH * 2);
            #pragma unroll
            for (int mi = 0; mi < 4; mi++)
                #pragma unroll
                for (int ni = 0; ni < 4; ni++)
                    MMA_F16(acc[mi][ni], ah[mi], &bhf[ni>>1][(ni&1)<<1]);

            if (TERMS == 3) {
                uint32_t blf[2][4];
                LDSM_X4(blf[0], bL + boff);
                LDSM_X4(blf[1], bL + boff + 16 * GPITCH * 2);
                #pragma unroll
                for (int mi = 0; mi < 4; mi++)
                    #pragma unroll
                    for (int ni = 0; ni < 4; ni++)
                        MMA_F16(acc[mi][ni], ah[mi], &blf[ni>>1][(ni&1)<<1]);
            }

            #pragma unroll
            for (int mi = 0; mi < 4; mi++)
                LDSM_X4(al[mi], aL + aoff + mi * 16 * GPITCH * 2);
            #pragma unroll
            for (int mi = 0; mi < 4; mi++)
                #pragma unroll
                for (int ni = 0; ni < 4; ni++)
                    MMA_F16(acc[mi][ni], al[mi], &bhf[ni>>1][(ni&1)<<1]);
        }
        __syncthreads();
        if (c + 2 < NC) LOAD_STAGE(s, c + 2);
    }
    #undef LOAD_STAGE

    // ---- epilogue ----
    const int g  = lane >> 2;
    const int cc = (lane & 3) << 1;
    #pragma unroll
    for (int mi = 0; mi < 4; mi++) {
        #pragma unroll
        for (int ni = 0; ni < 4; ni++) {
            int col = (int)bn + wn + ni * 8 + cc;
            if (col >= Nreal) continue;
            long row0 = bm + wm + mi * 16 + g;
            float v0 = acc[mi][ni][0], v1 = acc[mi][ni][1];
            float v2 = acc[mi][ni][2], v3 = acc[mi][ni][3];
            if (mode == 1) {
                float b0 = ext[col], b1 = ext[col + 1];
                v0 += b0; v1 += b1; v2 += b0; v3 += b1;
                v0 = (v0 > 20.f) ? v0 : log1pf(__expf(v0));
                v1 = (v1 > 20.f) ? v1 : log1pf(__expf(v1));
                v2 = (v2 > 20.f) ? v2 : log1pf(__expf(v2));
                v3 = (v3 > 20.f) ? v3 : log1pf(__expf(v3));
            }
            *(float2*)(C + row0 * ldc + col)       = make_float2(v0, v1);
            *(float2*)(C + (row0 + 8) * ldc + col) = make_float2(v2, v3);
        }
    }
}

// ================= launch =================
extern "C" void kernel_launch(void* const* d_in, const int* in_sizes, int n_in,
                              void* d_out, int out_size)
{
    const int*   ids    = (const int*)  d_in[0];
    const float* emb    = (const float*)d_in[1];
    const float* normw  = (const float*)d_in[2];
    const float* inpw   = (const float*)d_in[3];
    const float* convw  = (const float*)d_in[4];
    const float* convb  = (const float*)d_in[5];
    const float* xprojw = (const float*)d_in[6];
    const float* dtpw   = (const float*)d_in[7];
    const float* dtpb   = (const float*)d_in[8];
    const float* Alog   = (const float*)d_in[9];
    const float* Dw     = (const float*)d_in[10];
    const float* outpw  = (const float*)d_in[11];
    const float* normf  = (const float*)d_in[12];
    float* out = (float*)d_out;

    float *x, *xr, *u, *xdbl, *delta, *part;
    cudaGetSymbolAddress((void**)&x,     g_x);
    cudaGetSymbolAddress((void**)&xr,    g_xr);
    cudaGetSymbolAddress((void**)&u,     g_u);
    cudaGetSymbolAddress((void**)&xdbl,  g_xdbl);
    cudaGetSymbolAddress((void**)&delta, g_delta);
    cudaGetSymbolAddress((void**)&part,  g_part);

    __half *emb_h, *emb_l, *inpw_h, *inpw_l, *outpw_h, *outpw_l;
    __half *xn_h, *xn_l, *u_h, *u_l, *y_h, *y_l;
    __half *xpw_h, *xpw_l, *dtw_h, *dtw_l, *xdp_h, *xdp_l;
    cudaGetSymbolAddress((void**)&emb_h,  g_emb_h);   cudaGetSymbolAddress((void**)&emb_l,  g_emb_l);
    cudaGetSymbolAddress((void**)&inpw_h, g_inpw_h);  cudaGetSymbolAddress((void**)&inpw_l, g_inpw_l);
    cudaGetSymbolAddress((void**)&outpw_h,g_outpw_h); cudaGetSymbolAddress((void**)&outpw_l,g_outpw_l);
    cudaGetSymbolAddress((void**)&xn_h,   g_xn_h);    cudaGetSymbolAddress((void**)&xn_l,   g_xn_l);
    cudaGetSymbolAddress((void**)&u_h,    g_u_h);     cudaGetSymbolAddress((void**)&u_l,    g_u_l);
    cudaGetSymbolAddress((void**)&y_h,    g_y_h);     cudaGetSymbolAddress((void**)&y_l,    g_y_l);
    cudaGetSymbolAddress((void**)&xpw_h,  g_xpw_h);   cudaGetSymbolAddress((void**)&xpw_l,  g_xpw_l);
    cudaGetSymbolAddress((void**)&dtw_h,  g_dtw_h);   cudaGetSymbolAddress((void**)&dtw_l,  g_dtw_l);
    cudaGetSymbolAddress((void**)&xdp_h,  g_xdp_h);   cudaGetSymbolAddress((void**)&xdp_l,  g_xdp_l);

    cudaFuncSetAttribute((const void*)mma_gemm<128,3>,
                         cudaFuncAttributeMaxDynamicSharedMemorySize, GSMEM(128));
    cudaFuncSetAttribute((const void*)mma_gemm<256,3>,
                         cudaFuncAttributeMaxDynamicSharedMemorySize, GSMEM(256));
    cudaFuncSetAttribute((const void*)mma_gemm<256,2>,
                         cudaFuncAttributeMaxDynamicSharedMemorySize, GSMEM(256));

    #define SPLIT4(src, n, h, l) \
        split4_kernel<<<((n)/4 + 255) / 256, 256>>>((const float4*)(src), (n)/4, \
            (__half2*)(h), (__half2*)(l))

    embed_kernel<<<M_ROWS, 256>>>(ids, emb, x);                               // 1
    SPLIT4(inpw, N_LAYER * 2 * D_INNER * D_MODEL, inpw_h, inpw_l);            // 2

    for (int lyr = 0; lyr < N_LAYER; lyr++) {
        rmsnorm_split_kernel<<<M_ROWS, 256>>>(x, normw + lyr * D_MODEL,
                                              xn_h, xn_l);                    // 3

        // in_proj BM=256 (profiled control, launch #4)
        mma_gemm<256,3><<<dim3(2*D_INNER/128, M_ROWS/256, 1), 512, GSMEM(256)>>>(
            xn_h, xn_l,
            inpw_h + (long)lyr * 2*D_INNER*D_MODEL,
            inpw_l + (long)lyr * 2*D_INNER*D_MODEL,
            D_MODEL, D_MODEL, xr, 2*D_INNER, 2*D_INNER, nullptr, 0, 0);

        conv_silu_split_kernel<<<(M_ROWS*D_INNER/4 + 255)/256, 256>>>(
            xr, convw + lyr * D_INNER*D_CONV, convb + lyr * D_INNER,
            u, (__half2*)u_h, (__half2*)u_l);

        {
            int n4 = 128 * D_INNER / 4;
            split_pad_rows4<<<(n4 + 255)/256, 256>>>(
                xprojw + (long)lyr * XDBL_COLS * D_INNER, XDBL_COLS, D_INNER, 128,
                (__half2*)xpw_h, (__half2*)xpw_l);
        }
        mma_gemm<128,3><<<dim3(1, M_ROWS/128, 8), 256, GSMEM(128)>>>(
            u_h, u_l, xpw_h, xpw_l,
            D_INNER, D_INNER/8, part, 128, 128, nullptr, 0, (long)M_ROWS*128);
        reduce_xp_kernel<<<(M_ROWS*128 + 255)/256, 256>>>(part, xdbl, xdp_h, xdp_l);

        {
            int n4 = D_INNER * 64 / 4;
            split_pad_cols4<<<(n4 + 255)/256, 256>>>(
                dtpw + (long)lyr * D_INNER * DT_RANK, D_INNER, DT_RANK,
                DT_RANK, 64, (__half2*)dtw_h, (__half2*)dtw_l);
        }
        mma_gemm<128,3><<<dim3(D_INNER/128, M_ROWS/128, 1), 256, GSMEM(128)>>>(
            xdp_h, xdp_l, dtw_h, dtw_l,
            64, 64, delta, D_INNER, D_INNER, dtpb + lyr * D_INNER, 1, 0);

        scan_kernel<<<(BATCH*D_INNER)/16, 256>>>(
            delta, u, xdbl, xr, Alog + (long)lyr * D_INNER*D_STATE,
            Dw + lyr * D_INNER, y_h, y_l);

        if (lyr == 0)
            SPLIT4(outpw, N_LAYER * D_MODEL * D_INNER, outpw_h, outpw_l);

        mma_gemm<128,3><<<dim3(D_MODEL/128, M_ROWS/128, 4), 256, GSMEM(128)>>>(
            y_h, y_l,
            outpw_h + (long)lyr * D_MODEL*D_INNER,
            outpw_l + (long)lyr * D_MODEL*D_INNER,
            D_INNER, D_INNER/4, part, D_MODEL, D_MODEL, nullptr, 0,
            (long)M_ROWS*D_MODEL);
        reduce_out_kernel<<<(M_ROWS*D_MODEL/4 + 255)/256, 256>>>(part, x);
    }

    SPLIT4(emb, VOCAB * D_MODEL, emb_h, emb_l);
    rmsnorm_split_kernel<<<M_ROWS, 256>>>(x, normf, xn_h, xn_l);

    // logits: BM=256, 2-term (A*Bh) — Bl never loaded
    mma_gemm<256,2><<<dim3(VOCAB/128, M_ROWS/256, 1), 512, GSMEM(256)>>>(
        xn_h, xn_l, emb_h, emb_l,
        D_MODEL, D_MODEL, out, VOCAB, VOCAB, nullptr, 0, 0);
}

// round 9
// speedup vs baseline: 1.2014x; 1.2014x over previous
#include <cuda_runtime.h>
#include <cuda_fp16.h>
#include <math.h>
#include <stdint.h>

// ---------------- model dims ----------------
#define BATCH      2
#define SEQ        1024
#define M_ROWS     (BATCH*SEQ)        // 2048
#define D_MODEL    768
#define D_INNER    1536
#define D_STATE    16
#define DT_RANK    48
#define D_CONV     4
#define XDBL_COLS  (DT_RANK + 2*D_STATE)   // 80
#define VOCAB      32000
#define N_LAYER    2
#define EPS        1e-5f

// ---------------- fp32 scratch ----------------
__device__ __align__(16) float g_x    [M_ROWS * D_MODEL];
__device__ __align__(16) float g_xr   [M_ROWS * 2 * D_INNER];
__device__ __align__(16) float g_u    [M_ROWS * D_INNER];
__device__ __align__(16) float g_xdbl [M_ROWS * XDBL_COLS];
__device__ __align__(16) float g_delta[M_ROWS * D_INNER];
__device__ __align__(16) float g_part [4 * M_ROWS * D_MODEL];

// ---------------- fp16 hi/lo split buffers ----------------
__device__ __align__(16) __half g_emb_h [VOCAB*D_MODEL];
__device__ __align__(16) __half g_emb_l [VOCAB*D_MODEL];   // unused by logits now; kept for layout
__device__ __align__(16) __half g_inpw_h[N_LAYER*2*D_INNER*D_MODEL];
__device__ __align__(16) __half g_inpw_l[N_LAYER*2*D_INNER*D_MODEL];
__device__ __align__(16) __half g_outpw_h[N_LAYER*D_MODEL*D_INNER];
__device__ __align__(16) __half g_outpw_l[N_LAYER*D_MODEL*D_INNER];
__device__ __align__(16) __half g_xn_h[M_ROWS*D_MODEL];
__device__ __align__(16) __half g_xn_l[M_ROWS*D_MODEL];
__device__ __align__(16) __half g_u_h [M_ROWS*D_INNER];
__device__ __align__(16) __half g_u_l [M_ROWS*D_INNER];
__device__ __align__(16) __half g_y_h [M_ROWS*D_INNER];
__device__ __align__(16) __half g_y_l [M_ROWS*D_INNER];
__device__ __align__(16) __half g_xpw_h[128*D_INNER];
__device__ __align__(16) __half g_xpw_l[128*D_INNER];
__device__ __align__(16) __half g_dtw_h[D_INNER*64];
__device__ __align__(16) __half g_dtw_l[D_INNER*64];
__device__ __align__(16) __half g_xdp_h[M_ROWS*64];
__device__ __align__(16) __half g_xdp_l[M_ROWS*64];

// ================= helpers =================
__device__ __forceinline__ void split2(float v, __half& h, __half& l) {
    h = __float2half_rn(v);
    l = __float2half_rn(v - __half2float(h));
}

// ================= small kernels =================
__global__ void embed_kernel(const int* __restrict__ ids,
                             const float* __restrict__ emb,
                             float* __restrict__ x)
{
    int row = blockIdx.x;
    int tok = ids[row];
    const float4* src = (const float4*)(emb + (long)tok * D_MODEL);
    float4* dst = (float4*)(x + (long)row * D_MODEL);
    for (int i = threadIdx.x; i < D_MODEL/4; i += blockDim.x) dst[i] = src[i];
}

__global__ void rmsnorm_split_kernel(const float* __restrict__ x,
                                     const float* __restrict__ w,
                                     __half* __restrict__ oh,
                                     __half* __restrict__ ol)
{
    __shared__ float red[8];
    int row = blockIdx.x;
    const float* xp = x + (long)row * D_MODEL;
    float s = 0.f;
    for (int i = threadIdx.x; i < D_MODEL; i += 256) { float v = xp[i]; s += v*v; }
    #pragma unroll
    for (int o = 16; o; o >>= 1) s += __shfl_xor_sync(0xffffffffu, s, o);
    if ((threadIdx.x & 31) == 0) red[threadIdx.x >> 5] = s;
    __syncthreads();
    if (threadIdx.x < 8) {
        float t = red[threadIdx.x];
        #pragma unroll
        for (int o = 4; o; o >>= 1) t += __shfl_xor_sync(0xffu, t, o);
        if (threadIdx.x == 0) red[0] = t;
    }
    __syncthreads();
    float scale = rsqrtf(red[0] / (float)D_MODEL + EPS);
    for (int i = threadIdx.x; i < D_MODEL; i += 256) {
        float v = xp[i] * scale * w[i];
        __half h, l; split2(v, h, l);
        oh[(long)row * D_MODEL + i] = h;
        ol[(long)row * D_MODEL + i] = l;
    }
}

__global__ void split4_kernel(const float4* __restrict__ s, int n4,
                              __half2* __restrict__ h, __half2* __restrict__ l)
{
    int i = blockIdx.x * blockDim.x + threadIdx.x;
    if (i >= n4) return;
    float4 v = s[i];
    __half hx,lx,hy,ly,hz,lz,hw,lw;
    split2(v.x,hx,lx); split2(v.y,hy,ly); split2(v.z,hz,lz); split2(v.w,hw,lw);
    h[2*i]   = __halves2half2(hx,hy);
    h[2*i+1] = __halves2half2(hz,hw);
    l[2*i]   = __halves2half2(lx,ly);
    l[2*i+1] = __halves2half2(lz,lw);
}

// fp32 -> fp16 rn only (no lo), vec4 — for logits B (emb)
__global__ void cvt4_kernel(const float4* __restrict__ s, int n4,
                            __half2* __restrict__ h)
{
    int i = blockIdx.x * blockDim.x + threadIdx.x;
    if (i >= n4) return;
    float4 v = s[i];
    h[2*i]   = __halves2half2(__float2half_rn(v.x), __float2half_rn(v.y));
    h[2*i+1] = __halves2half2(__float2half_rn(v.z), __float2half_rn(v.w));
}

__global__ void split_pad_rows4(const float* __restrict__ s, int rows_real, int K,
                                int rows_pad,
                                __half2* __restrict__ h, __half2* __restrict__ l)
{
    int i = blockIdx.x * blockDim.x + threadIdx.x;
    int n4 = rows_pad * K / 4;
    if (i >= n4) return;
    int r = (i*4) / K;
    float4 v = (r < rows_real) ? *(const float4*)(s + (long)(i*4))
                               : make_float4(0,0,0,0);
    __half hx,lx,hy,ly,hz,lz,hw,lw;
    split2(v.x,hx,lx); split2(v.y,hy,ly); split2(v.z,hz,lz); split2(v.w,hw,lw);
    h[2*i]   = __halves2half2(hx,hy);
    h[2*i+1] = __halves2half2(hz,hw);
    l[2*i]   = __halves2half2(lx,ly);
    l[2*i+1] = __halves2half2(lz,lw);
}

__global__ void split_pad_cols4(const float* __restrict__ s, int rows, int src_ld,
                                int k_take, int k_pad,
                                __half2* __restrict__ h, __half2* __restrict__ l)
{
    int i = blockIdx.x * blockDim.x + threadIdx.x;
    int n4 = rows * k_pad / 4;
    if (i >= n4) return;
    int kp4 = k_pad / 4;
    int r = i / kp4, k = (i % kp4) * 4;
    float4 v = (k < k_take) ? *(const float4*)(s + (long)r * src_ld + k)
                            : make_float4(0,0,0,0);
    __half hx,lx,hy,ly,hz,lz,hw,lw;
    split2(v.x,hx,lx); split2(v.y,hy,ly); split2(v.z,hz,lz); split2(v.w,hw,lw);
    h[2*i]   = __halves2half2(hx,hy);
    h[2*i+1] = __halves2half2(hz,hw);
    l[2*i]   = __halves2half2(lx,ly);
    l[2*i+1] = __halves2half2(lz,lw);
}

__global__ void conv_silu_split_kernel(const float* __restrict__ xr,
                                       const float* __restrict__ cw,
                                       const float* __restrict__ cb,
                                       float* __restrict__ u,
                                       __half2* __restrict__ uh,
                                       __half2* __restrict__ ul)
{
    int i = blockIdx.x * blockDim.x + threadIdx.x;
    if (i >= M_ROWS * D_INNER / 4) return;
    int c = (i*4) % D_INNER;
    int m = (i*4) / D_INNER;
    int l = m % SEQ;
    const float* base = xr + (long)m * (2*D_INNER) + c;
    float4 v0  = *(const float4*)base;
    float4 vm1 = (l >= 1) ? *(const float4*)(base - 1*(2*D_INNER)) : make_float4(0,0,0,0);
    float4 vm2 = (l >= 2) ? *(const float4*)(base - 2*(2*D_INNER)) : make_float4(0,0,0,0);
    float4 vm3 = (l >= 3) ? *(const float4*)(base - 3*(2*D_INNER)) : make_float4(0,0,0,0);
    float4 cbv = *(const float4*)(cb + c);
    const float* p0 = &v0.x; const float* p1 = &vm1.x;
    const float* p2 = &vm2.x; const float* p3 = &vm3.x;
    const float* pb = &cbv.x;
    float o[4];
    #pragma unroll
    for (int t = 0; t < 4; t++) {
        float4 w = *(const float4*)(cw + (c + t) * 4);
        float acc = pb[t] + w.w * p0[t] + w.z * p1[t] + w.y * p2[t] + w.x * p3[t];
        o[t] = acc / (1.f + __expf(-acc));
    }
    *(float4*)(u + (long)i*4) = make_float4(o[0], o[1], o[2], o[3]);
    __half hx,lx,hy,ly,hz,lz,hw,lw;
    split2(o[0],hx,lx); split2(o[1],hy,ly); split2(o[2],hz,lz); split2(o[3],hw,lw);
    uh[2*i]   = __halves2half2(hx,hy);
    uh[2*i+1] = __halves2half2(hz,hw);
    ul[2*i]   = __halves2half2(lx,ly);
    ul[2*i+1] = __halves2half2(lz,lw);
}

__global__ void reduce_xp_kernel(const float* __restrict__ p,
                                 float* __restrict__ xdbl,
                                 __half* __restrict__ xdph,
                                 __half* __restrict__ xdpl)
{
    int i = blockIdx.x * blockDim.x + threadIdx.x;
    if (i >= M_ROWS * 128) return;
    int r = i >> 7, c = i & 127;
    const long S = (long)M_ROWS * 128;
    float s = 0.f;
    #pragma unroll
    for (int z = 0; z < 8; z++) s += p[z*S + i];
    if (c < XDBL_COLS) xdbl[(long)r * XDBL_COLS + c] = s;
    if (c < 64) {
        float v = (c < DT_RANK) ? s : 0.f;
        __half h, l; split2(v, h, l);
        xdph[(long)r*64 + c] = h;
        xdpl[(long)r*64 + c] = l;
    }
}

__global__ void reduce_out_kernel(const float* __restrict__ p,
                                  float* __restrict__ x)
{
    int i = blockIdx.x * blockDim.x + threadIdx.x;
    if (i >= M_ROWS * D_MODEL / 4) return;
    const long S4 = (long)M_ROWS * D_MODEL / 4;
    const float4* p4 = (const float4*)p;
    float4 a = ((float4*)x)[i];
    #pragma unroll
    for (int z = 0; z < 4; z++) {
        float4 b = p4[z*S4 + i];
        a.x += b.x; a.y += b.y; a.z += b.z; a.w += b.w;
    }
    ((float4*)x)[i] = a;
}

// selective scan: 4 states per lane (quad per channel), 2-shfl reduce,
// float4 B/C loads, software-pipelined; D skip + silu gate + fp16 split.
// blockDim 128 -> 32 channels/block; grid = 3072/32 = 96.
__global__ void scan_kernel(const float* __restrict__ delta,
                            const float* __restrict__ u,
                            const float* __restrict__ xdbl,
                            const float* __restrict__ xr,
                            const float* __restrict__ A_log,
                            const float* __restrict__ Dp,
                            __half* __restrict__ yh,
                            __half* __restrict__ yl)
{
    int gid = blockIdx.x * (blockDim.x / 4) + (threadIdx.x >> 2);
    int q   = threadIdx.x & 3;           // quad lane: states 4q..4q+3
    if (gid >= BATCH * D_INNER) return;
    int b  = gid / D_INNER;
    int di = gid % D_INNER;

    float An0 = -__expf(A_log[di * D_STATE + q*4 + 0]);
    float An1 = -__expf(A_log[di * D_STATE + q*4 + 1]);
    float An2 = -__expf(A_log[di * D_STATE + q*4 + 2]);
    float An3 = -__expf(A_log[di * D_STATE + q*4 + 3]);
    float Dv = Dp[di];
    float h0 = 0.f, h1 = 0.f, h2 = 0.f, h3 = 0.f;

    long m0 = (long)b * SEQ;
    const float* dptr = delta + m0 * D_INNER + di;
    const float* uptr = u     + m0 * D_INNER + di;
    const float* rptr = xr    + m0 * (2*D_INNER) + D_INNER + di;
    const float* bptr = xdbl  + m0 * XDBL_COLS + DT_RANK + q*4;
    const float* cptr = xdbl  + m0 * XDBL_COLS + DT_RANK + D_STATE + q*4;
    __half* yhp = yh + m0 * D_INNER + di;
    __half* ylp = yl + m0 * D_INNER + di;

    float dv = dptr[0], uv = uptr[0], rv = rptr[0];
    float4 Bv = *(const float4*)bptr;
    float4 Cv = *(const float4*)cptr;

    for (int l = 0; l < SEQ; l++) {
        float dv_n = 0.f, uv_n = 0.f, rv_n = 0.f;
        float4 Bv_n = make_float4(0,0,0,0), Cv_n = Bv_n;
        if (l + 1 < SEQ) {
            long ln = l + 1;
            dv_n = dptr[ln * D_INNER];
            uv_n = uptr[ln * D_INNER];
            rv_n = rptr[ln * (2*D_INNER)];
            Bv_n = *(const float4*)(bptr + ln * XDBL_COLS);
            Cv_n = *(const float4*)(cptr + ln * XDBL_COLS);
        }

        float du = dv * uv;
        h0 = fmaf(__expf(dv * An0), h0, du * Bv.x);
        h1 = fmaf(__expf(dv * An1), h1, du * Bv.y);
        h2 = fmaf(__expf(dv * An2), h2, du * Bv.z);
        h3 = fmaf(__expf(dv * An3), h3, du * Bv.w);
        float p = fmaf(h0, Cv.x, h1 * Cv.y) + fmaf(h2, Cv.z, h3 * Cv.w);
        p += __shfl_xor_sync(0xffffffffu, p, 2);
        p += __shfl_xor_sync(0xffffffffu, p, 1);
        if (q == 0) {
            float yv = (p + uv * Dv) * (rv / (1.f + __expf(-rv)));
            __half hb, lb; split2(yv, hb, lb);
            yhp[(long)l * D_INNER] = hb;
            ylp[(long)l * D_INNER] = lb;
        }
        dv = dv_n; uv = uv_n; rv = rv_n; Bv = Bv_n; Cv = Cv_n;
    }
}

// ================= mma.sync split-fp16 GEMM =================
// 128x128x32 tiles, 8 warps (2Mx4N), 2-stage cp.async, ldmatrix.x4 A+B.
// TERMS=3: D = Ah*Bh + Ah*Bl + Al*Bh
// TERMS=1: D = Ah*Bh (Al, Bl never loaded)
// mode 0: plain (C += z*zstride)   mode 1: softplus(acc + ext[col])
#define GPITCH 40

__device__ __forceinline__ uint32_t smem_u32(const void* p) {
    uint32_t a;
    asm("{ .reg .u64 t; cvta.to.shared.u64 t, %1; cvt.u32.u64 %0, t; }" : "=r"(a) : "l"(p));
    return a;
}

#define LDSM_X4(r, addr) \
    asm volatile("ldmatrix.sync.aligned.m8n8.x4.shared.b16 {%0,%1,%2,%3}, [%4];" \
        : "=r"((r)[0]),"=r"((r)[1]),"=r"((r)[2]),"=r"((r)[3]) : "r"(addr))

#define MMA_F16(c, a, b) \
    asm volatile("mma.sync.aligned.m16n8k16.row.col.f32.f16.f16.f32 " \
        "{%0,%1,%2,%3},{%4,%5,%6,%7},{%8,%9},{%0,%1,%2,%3};" \
        : "+f"((c)[0]),"+f"((c)[1]),"+f"((c)[2]),"+f"((c)[3]) \
        : "r"((a)[0]),"r"((a)[1]),"r"((a)[2]),"r"((a)[3]),"r"((b)[0]),"r"((b)[1]))

#define CP16(dst, src) \
    asm volatile("cp.async.cg.shared.global [%0], [%1], 16;" :: "r"(dst), "l"(src))
#define CP_COMMIT() asm volatile("cp.async.commit_group;" ::: "memory")
#define CP_WAIT(n)  asm volatile("cp.async.wait_group %0;" :: "n"(n) : "memory")

#define STAGE_ELEMS (512 * GPITCH)
#define GSMEM_BYTES (2 * STAGE_ELEMS * 2)    // 81920 B

template<int TERMS>
__global__ void __launch_bounds__(256, 2) mma_gemm(
    const __half* __restrict__ Ah, const __half* __restrict__ Al,
    const __half* __restrict__ Bh, const __half* __restrict__ Bl,
    int lda, int klen,
    float* __restrict__ C, int ldc, int Nreal,
    const float* __restrict__ ext, int mode, long zstride)
{
    extern __shared__ __half sm[];
    const uint32_t sbase = smem_u32(sm);
    const int tid  = threadIdx.x;
    const int lane = tid & 31;
    const int w    = tid >> 5;
    const int wm   = (w >> 2) << 6;
    const int wn   = (w & 3) << 5;
    const long bm  = (long)blockIdx.y * 128;
    const long bn  = (long)blockIdx.x * 128;
    const int koff = blockIdx.z * klen;
    C += (long)blockIdx.z * zstride;

    float acc[4][4][4];
    #pragma unroll
    for (int i = 0; i < 4; i++)
        #pragma unroll
        for (int j = 0; j < 4; j++)
            #pragma unroll
            for (int e = 0; e < 4; e++) acc[i][j][e] = 0.f;

    const int NC = klen >> 5;

    #define LOAD_STAGE(st, kc) do {                                           \
        int _k0 = koff + ((kc) << 5);                                         \
        _Pragma("unroll")                                                     \
        for (int _it = 0; _it < 8; _it++) {                                   \
            int _i = _it * 256 + tid;                                         \
            int _rg = _i >> 2, _ch = _i & 3;                                  \
            if (TERMS == 1 && _rg >= 128 && _rg < 256) continue;  /* skip Al */\
            if (TERMS == 1 && _rg >= 384) continue;               /* skip Bl */\
            const __half* _gb; long _grow;                                    \
            if (_rg < 256) {                                                  \
                int _a = _rg >= 128;                                          \
                _gb = _a ? Al : Ah; _grow = bm + (_rg - _a * 128);            \
            } else {                                                          \
                int _rb = _rg - 256;                                          \
                int _a = _rb >= 128;                                          \
                _gb = _a ? Bl : Bh; _grow = bn + (_rb - _a * 128);            \
            }                                                                 \
            const void* _src = _gb + _grow * (long)lda + _k0 + _ch * 8;       \
            uint32_t _dst = sbase + ((st) * STAGE_ELEMS + _rg * GPITCH        \
                                     + _ch * 8) * 2;                          \
            CP16(_dst, _src);                                                 \
        }                                                                     \
        CP_COMMIT();                                                          \
    } while (0)

    LOAD_STAGE(0, 0);
    LOAD_STAGE(1, 1);

    for (int c = 0; c < NC; c++) {
        if (c + 1 < NC) CP_WAIT(1);
        else            CP_WAIT(0);
        __syncthreads();

        const int s = c & 1;
        const uint32_t stg = sbase + (s * STAGE_ELEMS) * 2;
        const uint32_t aH = stg;
        const uint32_t aL = stg + (128 * GPITCH) * 2;
        const uint32_t bH = stg + (256 * GPITCH) * 2;
        const uint32_t bL = stg + (384 * GPITCH) * 2;

        #pragma unroll
        for (int ks = 0; ks < 2; ks++) {
            const int k0 = ks << 4;
            const uint32_t aoff = ((wm + (lane & 15)) * GPITCH
                                   + k0 + ((lane >> 4) << 3)) * 2;
            const int brow = wn + (lane & 7) + ((lane >> 4) << 3);
            const uint32_t boff = (brow * GPITCH + k0 + (((lane >> 3) & 1) << 3)) * 2;

            uint32_t ah[4][4];
            uint32_t bhf[2][4];
            #pragma unroll
            for (int mi = 0; mi < 4; mi++)
                LDSM_X4(ah[mi], aH + aoff + mi * 16 * GPITCH * 2);
            LDSM_X4(bhf[0], bH + boff);
            LDSM_X4(bhf[1], bH + boff + 16 * GPITCH * 2);
            #pragma unroll
            for (int mi = 0; mi < 4; mi++)
                #pragma unroll
                for (int ni = 0; ni < 4; ni++)
                    MMA_F16(acc[mi][ni], ah[mi], &bhf[ni>>1][(ni&1)<<1]);

            if (TERMS == 3) {
                uint32_t blf[2][4];
                LDSM_X4(blf[0], bL + boff);
                LDSM_X4(blf[1], bL + boff + 16 * GPITCH * 2);
                #pragma unroll
                for (int mi = 0; mi < 4; mi++)
                    #pragma unroll
                    for (int ni = 0; ni < 4; ni++)
                        MMA_F16(acc[mi][ni], ah[mi], &blf[ni>>1][(ni&1)<<1]);

                uint32_t al[4][4];
                #pragma unroll
                for (int mi = 0; mi < 4; mi++)
                    LDSM_X4(al[mi], aL + aoff + mi * 16 * GPITCH * 2);
                #pragma unroll
                for (int mi = 0; mi < 4; mi++)
                    #pragma unroll
                    for (int ni = 0; ni < 4; ni++)
                        MMA_F16(acc[mi][ni], al[mi], &bhf[ni>>1][(ni&1)<<1]);
            }
        }
        __syncthreads();
        if (c + 2 < NC) LOAD_STAGE(s, c + 2);
    }
    #undef LOAD_STAGE

    // ---- epilogue ----
    const int g  = lane >> 2;
    const int cc = (lane & 3) << 1;
    #pragma unroll
    for (int mi = 0; mi < 4; mi++) {
        #pragma unroll
        for (int ni = 0; ni < 4; ni++) {
            int col = (int)bn + wn + ni * 8 + cc;
            if (col >= Nreal) continue;
            long row0 = bm + wm + mi * 16 + g;
            float v0 = acc[mi][ni][0], v1 = acc[mi][ni][1];
            float v2 = acc[mi][ni][2], v3 = acc[mi][ni][3];
            if (mode == 1) {
                float b0 = ext[col], b1 = ext[col + 1];
                v0 += b0; v1 += b1; v2 += b0; v3 += b1;
                v0 = (v0 > 20.f) ? v0 : log1pf(__expf(v0));
                v1 = (v1 > 20.f) ? v1 : log1pf(__expf(v1));
                v2 = (v2 > 20.f) ? v2 : log1pf(__expf(v2));
                v3 = (v3 > 20.f) ? v3 : log1pf(__expf(v3));
            }
            *(float2*)(C + row0 * ldc + col)       = make_float2(v0, v1);
            *(float2*)(C + (row0 + 8) * ldc + col) = make_float2(v2, v3);
        }
    }
}

// ================= launch =================
extern "C" void kernel_launch(void* const* d_in, const int* in_sizes, int n_in,
                              void* d_out, int out_size)
{
    const int*   ids    = (const int*)  d_in[0];
    const float* emb    = (const float*)d_in[1];
    const float* normw  = (const float*)d_in[2];
    const float* inpw   = (const float*)d_in[3];
    const float* convw  = (const float*)d_in[4];
    const float* convb  = (const float*)d_in[5];
    const float* xprojw = (const float*)d_in[6];
    const float* dtpw   = (const float*)d_in[7];
    const float* dtpb   = (const float*)d_in[8];
    const float* Alog   = (const float*)d_in[9];
    const float* Dw     = (const float*)d_in[10];
    const float* outpw  = (const float*)d_in[11];
    const float* normf  = (const float*)d_in[12];
    float* out = (float*)d_out;

    float *x, *xr, *u, *xdbl, *delta, *part;
    cudaGetSymbolAddress((void**)&x,     g_x);
    cudaGetSymbolAddress((void**)&xr,    g_xr);
    cudaGetSymbolAddress((void**)&u,     g_u);
    cudaGetSymbolAddress((void**)&xdbl,  g_xdbl);
    cudaGetSymbolAddress((void**)&delta, g_delta);
    cudaGetSymbolAddress((void**)&part,  g_part);

    __half *emb_h, *inpw_h, *inpw_l, *outpw_h, *outpw_l;
    __half *xn_h, *xn_l, *u_h, *u_l, *y_h, *y_l;
    __half *xpw_h, *xpw_l, *dtw_h, *dtw_l, *xdp_h, *xdp_l;
    cudaGetSymbolAddress((void**)&emb_h,  g_emb_h);
    cudaGetSymbolAddress((void**)&inpw_h, g_inpw_h);  cudaGetSymbolAddress((void**)&inpw_l, g_inpw_l);
    cudaGetSymbolAddress((void**)&outpw_h,g_outpw_h); cudaGetSymbolAddress((void**)&outpw_l,g_outpw_l);
    cudaGetSymbolAddress((void**)&xn_h,   g_xn_h);    cudaGetSymbolAddress((void**)&xn_l,   g_xn_l);
    cudaGetSymbolAddress((void**)&u_h,    g_u_h);     cudaGetSymbolAddress((void**)&u_l,    g_u_l);
    cudaGetSymbolAddress((void**)&y_h,    g_y_h);     cudaGetSymbolAddress((void**)&y_l,    g_y_l);
    cudaGetSymbolAddress((void**)&xpw_h,  g_xpw_h);   cudaGetSymbolAddress((void**)&xpw_l,  g_xpw_l);
    cudaGetSymbolAddress((void**)&dtw_h,  g_dtw_h);   cudaGetSymbolAddress((void**)&dtw_l,  g_dtw_l);
    cudaGetSymbolAddress((void**)&xdp_h,  g_xdp_h);   cudaGetSymbolAddress((void**)&xdp_l,  g_xdp_l);

    cudaFuncSetAttribute((const void*)mma_gemm<3>,
                         cudaFuncAttributeMaxDynamicSharedMemorySize, GSMEM_BYTES);
    cudaFuncSetAttribute((const void*)mma_gemm<1>,
                         cudaFuncAttributeMaxDynamicSharedMemorySize, GSMEM_BYTES);

    #define SPLIT4(src, n, h, l) \
        split4_kernel<<<((n)/4 + 255) / 256, 256>>>((const float4*)(src), (n)/4, \
            (__half2*)(h), (__half2*)(l))

    embed_kernel<<<M_ROWS, 256>>>(ids, emb, x);                               // 1
    SPLIT4(inpw, N_LAYER * 2 * D_INNER * D_MODEL, inpw_h, inpw_l);            // 2

    for (int lyr = 0; lyr < N_LAYER; lyr++) {
        rmsnorm_split_kernel<<<M_ROWS, 256>>>(x, normw + lyr * D_MODEL,
                                              xn_h, xn_l);                    // 3

        // in_proj BM=128 (profiled control, launch #4)
        mma_gemm<3><<<dim3(2*D_INNER/128, M_ROWS/128, 1), 256, GSMEM_BYTES>>>(
            xn_h, xn_l,
            inpw_h + (long)lyr * 2*D_INNER*D_MODEL,
            inpw_l + (long)lyr * 2*D_INNER*D_MODEL,
            D_MODEL, D_MODEL, xr, 2*D_INNER, 2*D_INNER, nullptr, 0, 0);

        conv_silu_split_kernel<<<(M_ROWS*D_INNER/4 + 255)/256, 256>>>(
            xr, convw + lyr * D_INNER*D_CONV, convb + lyr * D_INNER,
            u, (__half2*)u_h, (__half2*)u_l);

        {
            int n4 = 128 * D_INNER / 4;
            split_pad_rows4<<<(n4 + 255)/256, 256>>>(
                xprojw + (long)lyr * XDBL_COLS * D_INNER, XDBL_COLS, D_INNER, 128,
                (__half2*)xpw_h, (__half2*)xpw_l);
        }
        mma_gemm<3><<<dim3(1, M_ROWS/128, 8), 256, GSMEM_BYTES>>>(
            u_h, u_l, xpw_h, xpw_l,
            D_INNER, D_INNER/8, part, 128, 128, nullptr, 0, (long)M_ROWS*128);
        reduce_xp_kernel<<<(M_ROWS*128 + 255)/256, 256>>>(part, xdbl, xdp_h, xdp_l);

        {
            int n4 = D_INNER * 64 / 4;
            split_pad_cols4<<<(n4 + 255)/256, 256>>>(
                dtpw + (long)lyr * D_INNER * DT_RANK, D_INNER, DT_RANK,
                DT_RANK, 64, (__half2*)dtw_h, (__half2*)dtw_l);
        }
        mma_gemm<3><<<dim3(D_INNER/128, M_ROWS/128, 1), 256, GSMEM_BYTES>>>(
            xdp_h, xdp_l, dtw_h, dtw_l,
            64, 64, delta, D_INNER, D_INNER, dtpb + lyr * D_INNER, 1, 0);

        scan_kernel<<<(BATCH*D_INNER)/32, 128>>>(
            delta, u, xdbl, xr, Alog + (long)lyr * D_INNER*D_STATE,
            Dw + lyr * D_INNER, y_h, y_l);

        if (lyr == 0)
            SPLIT4(outpw, N_LAYER * D_MODEL * D_INNER, outpw_h, outpw_l);

        mma_gemm<3><<<dim3(D_MODEL/128, M_ROWS/128, 4), 256, GSMEM_BYTES>>>(
            y_h, y_l,
            outpw_h + (long)lyr * D_MODEL*D_INNER,
            outpw_l + (long)lyr * D_MODEL*D_INNER,
            D_INNER, D_INNER/4, part, D_MODEL, D_MODEL, nullptr, 0,
            (long)M_ROWS*D_MODEL);
        reduce_out_kernel<<<(M_ROWS*D_MODEL/4 + 255)/256, 256>>>(part, x);
    }

    // emb hi-only conversion (Bl never needed by 1-term logits)
    cvt4_kernel<<<((VOCAB*D_MODEL)/4 + 255)/256, 256>>>(
        (const float4*)emb, VOCAB*D_MODEL/4, (__half2*)emb_h);
    rmsnorm_split_kernel<<<M_ROWS, 256>>>(x, normf, xn_h, xn_l);

    // logits: 1-term (Ah*Bh) — Al and Bl never loaded
    mma_gemm<1><<<dim3(VOCAB/128, M_ROWS/128, 1), 256, GSMEM_BYTES>>>(
        xn_h, xn_l, emb_h, nullptr,
        D_MODEL, D_MODEL, out, VOCAB, VOCAB, nullptr, 0, 0);
}

// round 10
// speedup vs baseline: 1.2931x; 1.0764x over previous
#include <cuda_runtime.h>
#include <cuda_fp16.h>
#include <math.h>
#include <stdint.h>

// ---------------- model dims ----------------
#define BATCH      2
#define SEQ        1024
#define M_ROWS     (BATCH*SEQ)        // 2048
#define D_MODEL    768
#define D_INNER    1536
#define D_STATE    16
#define DT_RANK    48
#define D_CONV     4
#define XDBL_COLS  (DT_RANK + 2*D_STATE)   // 80
#define VOCAB      32000
#define N_LAYER    2
#define EPS        1e-5f

// ---------------- fp32 scratch ----------------
__device__ __align__(16) float g_x    [M_ROWS * D_MODEL];
__device__ __align__(16) float g_xr   [M_ROWS * 2 * D_INNER];
__device__ __align__(16) float g_u    [M_ROWS * D_INNER];
__device__ __align__(16) float g_xdbl [M_ROWS * XDBL_COLS];
__device__ __align__(16) float g_delta[M_ROWS * D_INNER];
__device__ __align__(16) float g_part [4 * M_ROWS * D_MODEL];

// ---------------- fp16 buffers ----------------
__device__ __align__(16) __half g_emb_h [VOCAB*D_MODEL];
__device__ __align__(16) __half g_inpw_h[N_LAYER*2*D_INNER*D_MODEL];
__device__ __align__(16) __half g_outpw_h[N_LAYER*D_MODEL*D_INNER];
__device__ __align__(16) __half g_xn_h[M_ROWS*D_MODEL];
__device__ __align__(16) __half g_xn_l[M_ROWS*D_MODEL];
__device__ __align__(16) __half g_u_h [M_ROWS*D_INNER];
__device__ __align__(16) __half g_u_l [M_ROWS*D_INNER];
__device__ __align__(16) __half g_y_h [M_ROWS*D_INNER];
__device__ __align__(16) __half g_y_l [M_ROWS*D_INNER];
__device__ __align__(16) __half g_xpw_h[128*D_INNER];
__device__ __align__(16) __half g_xpw_l[128*D_INNER];
__device__ __align__(16) __half g_dtw_h[D_INNER*64];
__device__ __align__(16) __half g_dtw_l[D_INNER*64];
__device__ __align__(16) __half g_xdp_h[M_ROWS*64];
__device__ __align__(16) __half g_xdp_l[M_ROWS*64];

// ================= helpers =================
__device__ __forceinline__ void split2(float v, __half& h, __half& l) {
    h = __float2half_rn(v);
    l = __float2half_rn(v - __half2float(h));
}

// ================= small kernels =================
__global__ void embed_kernel(const int* __restrict__ ids,
                             const float* __restrict__ emb,
                             float* __restrict__ x)
{
    int row = blockIdx.x;
    int tok = ids[row];
    const float4* src = (const float4*)(emb + (long)tok * D_MODEL);
    float4* dst = (float4*)(x + (long)row * D_MODEL);
    for (int i = threadIdx.x; i < D_MODEL/4; i += blockDim.x) dst[i] = src[i];
}

__global__ void rmsnorm_split_kernel(const float* __restrict__ x,
                                     const float* __restrict__ w,
                                     __half* __restrict__ oh,
                                     __half* __restrict__ ol)
{
    __shared__ float red[8];
    int row = blockIdx.x;
    const float* xp = x + (long)row * D_MODEL;
    float s = 0.f;
    for (int i = threadIdx.x; i < D_MODEL; i += 256) { float v = xp[i]; s += v*v; }
    #pragma unroll
    for (int o = 16; o; o >>= 1) s += __shfl_xor_sync(0xffffffffu, s, o);
    if ((threadIdx.x & 31) == 0) red[threadIdx.x >> 5] = s;
    __syncthreads();
    if (threadIdx.x < 8) {
        float t = red[threadIdx.x];
        #pragma unroll
        for (int o = 4; o; o >>= 1) t += __shfl_xor_sync(0xffu, t, o);
        if (threadIdx.x == 0) red[0] = t;
    }
    __syncthreads();
    float scale = rsqrtf(red[0] / (float)D_MODEL + EPS);
    for (int i = threadIdx.x; i < D_MODEL; i += 256) {
        float v = xp[i] * scale * w[i];
        __half h, l; split2(v, h, l);
        oh[(long)row * D_MODEL + i] = h;
        ol[(long)row * D_MODEL + i] = l;
    }
}

// fp32 -> fp16 rn only, vec4 (for weight hi buffers)
__global__ void cvt4_kernel(const float4* __restrict__ s, int n4,
                            __half2* __restrict__ h)
{
    int i = blockIdx.x * blockDim.x + threadIdx.x;
    if (i >= n4) return;
    float4 v = s[i];
    h[2*i]   = __halves2half2(__float2half_rn(v.x), __float2half_rn(v.y));
    h[2*i+1] = __halves2half2(__float2half_rn(v.z), __float2half_rn(v.w));
}

__global__ void split_pad_rows4(const float* __restrict__ s, int rows_real, int K,
                                int rows_pad,
                                __half2* __restrict__ h, __half2* __restrict__ l)
{
    int i = blockIdx.x * blockDim.x + threadIdx.x;
    int n4 = rows_pad * K / 4;
    if (i >= n4) return;
    int r = (i*4) / K;
    float4 v = (r < rows_real) ? *(const float4*)(s + (long)(i*4))
                               : make_float4(0,0,0,0);
    __half hx,lx,hy,ly,hz,lz,hw,lw;
    split2(v.x,hx,lx); split2(v.y,hy,ly); split2(v.z,hz,lz); split2(v.w,hw,lw);
    h[2*i]   = __halves2half2(hx,hy);
    h[2*i+1] = __halves2half2(hz,hw);
    l[2*i]   = __halves2half2(lx,ly);
    l[2*i+1] = __halves2half2(lz,lw);
}

__global__ void split_pad_cols4(const float* __restrict__ s, int rows, int src_ld,
                                int k_take, int k_pad,
                                __half2* __restrict__ h, __half2* __restrict__ l)
{
    int i = blockIdx.x * blockDim.x + threadIdx.x;
    int n4 = rows * k_pad / 4;
    if (i >= n4) return;
    int kp4 = k_pad / 4;
    int r = i / kp4, k = (i % kp4) * 4;
    float4 v = (k < k_take) ? *(const float4*)(s + (long)r * src_ld + k)
                            : make_float4(0,0,0,0);
    __half hx,lx,hy,ly,hz,lz,hw,lw;
    split2(v.x,hx,lx); split2(v.y,hy,ly); split2(v.z,hz,lz); split2(v.w,hw,lw);
    h[2*i]   = __halves2half2(hx,hy);
    h[2*i+1] = __halves2half2(hz,hw);
    l[2*i]   = __halves2half2(lx,ly);
    l[2*i+1] = __halves2half2(lz,lw);
}

__global__ void conv_silu_split_kernel(const float* __restrict__ xr,
                                       const float* __restrict__ cw,
                                       const float* __restrict__ cb,
                                       float* __restrict__ u,
                                       __half2* __restrict__ uh,
                                       __half2* __restrict__ ul)
{
    int i = blockIdx.x * blockDim.x + threadIdx.x;
    if (i >= M_ROWS * D_INNER / 4) return;
    int c = (i*4) % D_INNER;
    int m = (i*4) / D_INNER;
    int l = m % SEQ;
    const float* base = xr + (long)m * (2*D_INNER) + c;
    float4 v0  = *(const float4*)base;
    float4 vm1 = (l >= 1) ? *(const float4*)(base - 1*(2*D_INNER)) : make_float4(0,0,0,0);
    float4 vm2 = (l >= 2) ? *(const float4*)(base - 2*(2*D_INNER)) : make_float4(0,0,0,0);
    float4 vm3 = (l >= 3) ? *(const float4*)(base - 3*(2*D_INNER)) : make_float4(0,0,0,0);
    float4 cbv = *(const float4*)(cb + c);
    const float* p0 = &v0.x; const float* p1 = &vm1.x;
    const float* p2 = &vm2.x; const float* p3 = &vm3.x;
    const float* pb = &cbv.x;
    float o[4];
    #pragma unroll
    for (int t = 0; t < 4; t++) {
        float4 w = *(const float4*)(cw + (c + t) * 4);
        float acc = pb[t] + w.w * p0[t] + w.z * p1[t] + w.y * p2[t] + w.x * p3[t];
        o[t] = acc / (1.f + __expf(-acc));
    }
    *(float4*)(u + (long)i*4) = make_float4(o[0], o[1], o[2], o[3]);
    __half hx,lx,hy,ly,hz,lz,hw,lw;
    split2(o[0],hx,lx); split2(o[1],hy,ly); split2(o[2],hz,lz); split2(o[3],hw,lw);
    uh[2*i]   = __halves2half2(hx,hy);
    uh[2*i+1] = __halves2half2(hz,hw);
    ul[2*i]   = __halves2half2(lx,ly);
    ul[2*i+1] = __halves2half2(lz,lw);
}

__global__ void reduce_xp_kernel(const float* __restrict__ p,
                                 float* __restrict__ xdbl,
                                 __half* __restrict__ xdph,
                                 __half* __restrict__ xdpl)
{
    int i = blockIdx.x * blockDim.x + threadIdx.x;
    if (i >= M_ROWS * 128) return;
    int r = i >> 7, c = i & 127;
    const long S = (long)M_ROWS * 128;
    float s = 0.f;
    #pragma unroll
    for (int z = 0; z < 8; z++) s += p[z*S + i];
    if (c < XDBL_COLS) xdbl[(long)r * XDBL_COLS + c] = s;
    if (c < 64) {
        float v = (c < DT_RANK) ? s : 0.f;
        __half h, l; split2(v, h, l);
        xdph[(long)r*64 + c] = h;
        xdpl[(long)r*64 + c] = l;
    }
}

__global__ void reduce_out_kernel(const float* __restrict__ p,
                                  float* __restrict__ x)
{
    int i = blockIdx.x * blockDim.x + threadIdx.x;
    if (i >= M_ROWS * D_MODEL / 4) return;
    const long S4 = (long)M_ROWS * D_MODEL / 4;
    const float4* p4 = (const float4*)p;
    float4 a = ((float4*)x)[i];
    #pragma unroll
    for (int z = 0; z < 4; z++) {
        float4 b = p4[z*S4 + i];
        a.x += b.x; a.y += b.y; a.z += b.z; a.w += b.w;
    }
    ((float4*)x)[i] = a;
}

// selective scan: 4 states per lane (quad per channel), 2-shfl reduce,
// float4 B/C loads, software-pipelined; D skip + silu gate + fp16 split.
__global__ void scan_kernel(const float* __restrict__ delta,
                            const float* __restrict__ u,
                            const float* __restrict__ xdbl,
                            const float* __restrict__ xr,
                            const float* __restrict__ A_log,
                            const float* __restrict__ Dp,
                            __half* __restrict__ yh,
                            __half* __restrict__ yl)
{
    int gid = blockIdx.x * (blockDim.x / 4) + (threadIdx.x >> 2);
    int q   = threadIdx.x & 3;
    if (gid >= BATCH * D_INNER) return;
    int b  = gid / D_INNER;
    int di = gid % D_INNER;

    float An0 = -__expf(A_log[di * D_STATE + q*4 + 0]);
    float An1 = -__expf(A_log[di * D_STATE + q*4 + 1]);
    float An2 = -__expf(A_log[di * D_STATE + q*4 + 2]);
    float An3 = -__expf(A_log[di * D_STATE + q*4 + 3]);
    float Dv = Dp[di];
    float h0 = 0.f, h1 = 0.f, h2 = 0.f, h3 = 0.f;

    long m0 = (long)b * SEQ;
    const float* dptr = delta + m0 * D_INNER + di;
    const float* uptr = u     + m0 * D_INNER + di;
    const float* rptr = xr    + m0 * (2*D_INNER) + D_INNER + di;
    const float* bptr = xdbl  + m0 * XDBL_COLS + DT_RANK + q*4;
    const float* cptr = xdbl  + m0 * XDBL_COLS + DT_RANK + D_STATE + q*4;
    __half* yhp = yh + m0 * D_INNER + di;
    __half* ylp = yl + m0 * D_INNER + di;

    float dv = dptr[0], uv = uptr[0], rv = rptr[0];
    float4 Bv = *(const float4*)bptr;
    float4 Cv = *(const float4*)cptr;

    for (int l = 0; l < SEQ; l++) {
        float dv_n = 0.f, uv_n = 0.f, rv_n = 0.f;
        float4 Bv_n = make_float4(0,0,0,0), Cv_n = Bv_n;
        if (l + 1 < SEQ) {
            long ln = l + 1;
            dv_n = dptr[ln * D_INNER];
            uv_n = uptr[ln * D_INNER];
            rv_n = rptr[ln * (2*D_INNER)];
            Bv_n = *(const float4*)(bptr + ln * XDBL_COLS);
            Cv_n = *(const float4*)(cptr + ln * XDBL_COLS);
        }

        float du = dv * uv;
        h0 = fmaf(__expf(dv * An0), h0, du * Bv.x);
        h1 = fmaf(__expf(dv * An1), h1, du * Bv.y);
        h2 = fmaf(__expf(dv * An2), h2, du * Bv.z);
        h3 = fmaf(__expf(dv * An3), h3, du * Bv.w);
        float p = fmaf(h0, Cv.x, h1 * Cv.y) + fmaf(h2, Cv.z, h3 * Cv.w);
        p += __shfl_xor_sync(0xffffffffu, p, 2);
        p += __shfl_xor_sync(0xffffffffu, p, 1);
        if (q == 0) {
            float yv = (p + uv * Dv) * (rv / (1.f + __expf(-rv)));
            __half hb, lb; split2(yv, hb, lb);
            yhp[(long)l * D_INNER] = hb;
            ylp[(long)l * D_INNER] = lb;
        }
        dv = dv_n; uv = uv_n; rv = rv_n; Bv = Bv_n; Cv = Cv_n;
    }
}

// ================= mma.sync split-fp16 GEMM =================
// 128x128x32 tiles, 8 warps (2Mx4N), ldmatrix.x4 A+B.
// TERMS=3: D = Ah*Bh + Ah*Bl + Al*Bh   (2-stage, double-sync; 512 smem rows)
// TERMS=2: D = Ah*Bh + Al*Bh           (3-stage, single-sync; 384 rows)
// TERMS=1: D = Ah*Bh                   (3-stage, single-sync; 256 rows)
// mode 0: plain (C += z*zstride)   mode 1: softplus(acc + ext[col])
#define GPITCH 40

__device__ __forceinline__ uint32_t smem_u32(const void* p) {
    uint32_t a;
    asm("{ .reg .u64 t; cvta.to.shared.u64 t, %1; cvt.u32.u64 %0, t; }" : "=r"(a) : "l"(p));
    return a;
}

#define LDSM_X4(r, addr) \
    asm volatile("ldmatrix.sync.aligned.m8n8.x4.shared.b16 {%0,%1,%2,%3}, [%4];" \
        : "=r"((r)[0]),"=r"((r)[1]),"=r"((r)[2]),"=r"((r)[3]) : "r"(addr))

#define MMA_F16(c, a, b) \
    asm volatile("mma.sync.aligned.m16n8k16.row.col.f32.f16.f16.f32 " \
        "{%0,%1,%2,%3},{%4,%5,%6,%7},{%8,%9},{%0,%1,%2,%3};" \
        : "+f"((c)[0]),"+f"((c)[1]),"+f"((c)[2]),"+f"((c)[3]) \
        : "r"((a)[0]),"r"((a)[1]),"r"((a)[2]),"r"((a)[3]),"r"((b)[0]),"r"((b)[1]))

#define CP16(dst, src) \
    asm volatile("cp.async.cg.shared.global [%0], [%1], 16;" :: "r"(dst), "l"(src))
#define CP_COMMIT() asm volatile("cp.async.commit_group;" ::: "memory")
#define CP_WAIT(n)  asm volatile("cp.async.wait_group %0;" :: "n"(n) : "memory")

template<int TERMS>
__global__ void __launch_bounds__(256, 2) mma_gemm(
    const __half* __restrict__ Ah, const __half* __restrict__ Al,
    const __half* __restrict__ Bh, const __half* __restrict__ Bl,
    int lda, int klen,
    float* __restrict__ C, int ldc, int Nreal,
    const float* __restrict__ ext, int mode, long zstride)
{
    constexpr int AROWS = (TERMS == 1) ? 128 : 256;
    constexpr int ROWS  = AROWS + ((TERMS == 3) ? 256 : 128);
    constexpr int SELEM = ROWS * GPITCH;
    constexpr int NS    = (TERMS == 3) ? 2 : 3;
    constexpr int LITER = ROWS / 64;

    extern __shared__ __half sm[];
    const uint32_t sbase = smem_u32(sm);
    const int tid  = threadIdx.x;
    const int lane = tid & 31;
    const int w    = tid >> 5;
    const int wm   = (w >> 2) << 6;
    const int wn   = (w & 3) << 5;
    const long bm  = (long)blockIdx.y * 128;
    const long bn  = (long)blockIdx.x * 128;
    const int koff = blockIdx.z * klen;
    C += (long)blockIdx.z * zstride;

    float acc[4][4][4];
    #pragma unroll
    for (int i = 0; i < 4; i++)
        #pragma unroll
        for (int j = 0; j < 4; j++)
            #pragma unroll
            for (int e = 0; e < 4; e++) acc[i][j][e] = 0.f;

    const int NC = klen >> 5;

    #define LOAD_STAGE(st, kc) do {                                           \
        int _k0 = koff + ((kc) << 5);                                         \
        _Pragma("unroll")                                                     \
        for (int _it = 0; _it < LITER; _it++) {                               \
            int _i = _it * 256 + tid;                                         \
            int _rg = _i >> 2, _ch = _i & 3;                                  \
            const __half* _gb; long _grow;                                    \
            if (_rg < 128)                    { _gb = Ah; _grow = bm + _rg; } \
            else if (TERMS >= 2 && _rg < 256) { _gb = Al; _grow = bm + _rg - 128; } \
            else if (_rg < AROWS + 128)       { _gb = Bh; _grow = bn + _rg - AROWS; } \
            else                              { _gb = Bl; _grow = bn + _rg - AROWS - 128; } \
            const void* _src = _gb + _grow * (long)lda + _k0 + _ch * 8;       \
            uint32_t _dst = sbase + ((st) * SELEM + _rg * GPITCH              \
                                     + _ch * 8) * 2;                          \
            CP16(_dst, _src);                                                 \
        }                                                                     \
        CP_COMMIT();                                                          \
    } while (0)

    #define MMA_BODY(stg) do {                                                \
        const uint32_t aH = (stg);                                            \
        const uint32_t aL = (stg) + (128 * GPITCH) * 2;                       \
        const uint32_t bH = (stg) + (AROWS * GPITCH) * 2;                     \
        const uint32_t bL = bH + (128 * GPITCH) * 2;                          \
        _Pragma("unroll")                                                     \
        for (int ks = 0; ks < 2; ks++) {                                      \
            const int k0 = ks << 4;                                           \
            const uint32_t aoff = ((wm + (lane & 15)) * GPITCH                \
                                   + k0 + ((lane >> 4) << 3)) * 2;            \
            const int brow = wn + (lane & 7) + ((lane >> 4) << 3);            \
            const uint32_t boff = (brow * GPITCH + k0                         \
                                   + (((lane >> 3) & 1) << 3)) * 2;           \
            uint32_t ah[4][4];                                                \
            uint32_t bhf[2][4];                                               \
            _Pragma("unroll")                                                 \
            for (int mi = 0; mi < 4; mi++)                                    \
                LDSM_X4(ah[mi], aH + aoff + mi * 16 * GPITCH * 2);            \
            LDSM_X4(bhf[0], bH + boff);                                       \
            LDSM_X4(bhf[1], bH + boff + 16 * GPITCH * 2);                     \
            _Pragma("unroll")                                                 \
            for (int mi = 0; mi < 4; mi++)                                    \
                _Pragma("unroll")                                             \
                for (int ni = 0; ni < 4; ni++)                                \
                    MMA_F16(acc[mi][ni], ah[mi], &bhf[ni>>1][(ni&1)<<1]);     \
            if (TERMS == 3) {                                                 \
                uint32_t blf[2][4];                                           \
                LDSM_X4(blf[0], bL + boff);                                   \
                LDSM_X4(blf[1], bL + boff + 16 * GPITCH * 2);                 \
                _Pragma("unroll")                                             \
                for (int mi = 0; mi < 4; mi++)                                \
                    _Pragma("unroll")                                         \
                    for (int ni = 0; ni < 4; ni++)                            \
                        MMA_F16(acc[mi][ni], ah[mi], &blf[ni>>1][(ni&1)<<1]); \
            }                                                                 \
            if (TERMS >= 2) {                                                 \
                uint32_t al[4][4];                                            \
                _Pragma("unroll")                                             \
                for (int mi = 0; mi < 4; mi++)                                \
                    LDSM_X4(al[mi], aL + aoff + mi * 16 * GPITCH * 2);        \
                _Pragma("unroll")                                             \
                for (int mi = 0; mi < 4; mi++)                                \
                    _Pragma("unroll")                                         \
                    for (int ni = 0; ni < 4; ni++)                            \
                        MMA_F16(acc[mi][ni], al[mi], &bhf[ni>>1][(ni&1)<<1]); \
            }                                                                 \
        }                                                                     \
    } while (0)

    LOAD_STAGE(0, 0);
    if (NC > 1) LOAD_STAGE(1, 1);

    if (NS == 2) {
        for (int c = 0; c < NC; c++) {
            if (c + 1 < NC) CP_WAIT(1);
            else            CP_WAIT(0);
            __syncthreads();
            MMA_BODY(sbase + ((c & 1) * SELEM) * 2);
            __syncthreads();
            if (c + 2 < NC) LOAD_STAGE(c & 1, c + 2);
        }
    } else {
        // 3-stage, single sync: top-of-loop barrier guarantees stage
        // (c+2)%3 (== (c-1)%3) was fully consumed by all warps.
        for (int c = 0; c < NC; c++) {
            if (c + 1 < NC) CP_WAIT(1);
            else            CP_WAIT(0);
            __syncthreads();
            if (c + 2 < NC) LOAD_STAGE((c + 2) % 3, c + 2);
            MMA_BODY(sbase + ((c % 3) * SELEM) * 2);
        }
    }
    #undef LOAD_STAGE
    #undef MMA_BODY

    // ---- epilogue ----
    const int g  = lane >> 2;
    const int cc = (lane & 3) << 1;
    #pragma unroll
    for (int mi = 0; mi < 4; mi++) {
        #pragma unroll
        for (int ni = 0; ni < 4; ni++) {
            int col = (int)bn + wn + ni * 8 + cc;
            if (col >= Nreal) continue;
            long row0 = bm + wm + mi * 16 + g;
            float v0 = acc[mi][ni][0], v1 = acc[mi][ni][1];
            float v2 = acc[mi][ni][2], v3 = acc[mi][ni][3];
            if (mode == 1) {
                float b0 = ext[col], b1 = ext[col + 1];
                v0 += b0; v1 += b1; v2 += b0; v3 += b1;
                v0 = (v0 > 20.f) ? v0 : log1pf(__expf(v0));
                v1 = (v1 > 20.f) ? v1 : log1pf(__expf(v1));
                v2 = (v2 > 20.f) ? v2 : log1pf(__expf(v2));
                v3 = (v3 > 20.f) ? v3 : log1pf(__expf(v3));
            }
            *(float2*)(C + row0 * ldc + col)       = make_float2(v0, v1);
            *(float2*)(C + (row0 + 8) * ldc + col) = make_float2(v2, v3);
        }
    }
}

#define GSMEM(TERMS) \
    ((((TERMS)==3) ? 2*512 : ((TERMS)==2) ? 3*384 : 3*256) * GPITCH * 2)

// ================= launch =================
extern "C" void kernel_launch(void* const* d_in, const int* in_sizes, int n_in,
                              void* d_out, int out_size)
{
    const int*   ids    = (const int*)  d_in[0];
    const float* emb    = (const float*)d_in[1];
    const float* normw  = (const float*)d_in[2];
    const float* inpw   = (const float*)d_in[3];
    const float* convw  = (const float*)d_in[4];
    const float* convb  = (const float*)d_in[5];
    const float* xprojw = (const float*)d_in[6];
    const float* dtpw   = (const float*)d_in[7];
    const float* dtpb   = (const float*)d_in[8];
    const float* Alog   = (const float*)d_in[9];
    const float* Dw     = (const float*)d_in[10];
    const float* outpw  = (const float*)d_in[11];
    const float* normf  = (const float*)d_in[12];
    float* out = (float*)d_out;

    float *x, *xr, *u, *xdbl, *delta, *part;
    cudaGetSymbolAddress((void**)&x,     g_x);
    cudaGetSymbolAddress((void**)&xr,    g_xr);
    cudaGetSymbolAddress((void**)&u,     g_u);
    cudaGetSymbolAddress((void**)&xdbl,  g_xdbl);
    cudaGetSymbolAddress((void**)&delta, g_delta);
    cudaGetSymbolAddress((void**)&part,  g_part);

    __half *emb_h, *inpw_h, *outpw_h;
    __half *xn_h, *xn_l, *u_h, *u_l, *y_h, *y_l;
    __half *xpw_h, *xpw_l, *dtw_h, *dtw_l, *xdp_h, *xdp_l;
    cudaGetSymbolAddress((void**)&emb_h,  g_emb_h);
    cudaGetSymbolAddress((void**)&inpw_h, g_inpw_h);
    cudaGetSymbolAddress((void**)&outpw_h,g_outpw_h);
    cudaGetSymbolAddress((void**)&xn_h,   g_xn_h);    cudaGetSymbolAddress((void**)&xn_l,   g_xn_l);
    cudaGetSymbolAddress((void**)&u_h,    g_u_h);     cudaGetSymbolAddress((void**)&u_l,    g_u_l);
    cudaGetSymbolAddress((void**)&y_h,    g_y_h);     cudaGetSymbolAddress((void**)&y_l,    g_y_l);
    cudaGetSymbolAddress((void**)&xpw_h,  g_xpw_h);   cudaGetSymbolAddress((void**)&xpw_l,  g_xpw_l);
    cudaGetSymbolAddress((void**)&dtw_h,  g_dtw_h);   cudaGetSymbolAddress((void**)&dtw_l,  g_dtw_l);
    cudaGetSymbolAddress((void**)&xdp_h,  g_xdp_h);   cudaGetSymbolAddress((void**)&xdp_l,  g_xdp_l);

    cudaFuncSetAttribute((const void*)mma_gemm<3>,
                         cudaFuncAttributeMaxDynamicSharedMemorySize, GSMEM(3));
    cudaFuncSetAttribute((const void*)mma_gemm<2>,
                         cudaFuncAttributeMaxDynamicSharedMemorySize, GSMEM(2));
    cudaFuncSetAttribute((const void*)mma_gemm<1>,
                         cudaFuncAttributeMaxDynamicSharedMemorySize, GSMEM(1));

    #define CVT4(src, n, h) \
        cvt4_kernel<<<((n)/4 + 255) / 256, 256>>>((const float4*)(src), (n)/4, \
            (__half2*)(h))

    embed_kernel<<<M_ROWS, 256>>>(ids, emb, x);                               // 1
    CVT4(inpw, N_LAYER * 2 * D_INNER * D_MODEL, inpw_h);                      // 2

    for (int lyr = 0; lyr < N_LAYER; lyr++) {
        rmsnorm_split_kernel<<<M_ROWS, 256>>>(x, normw + lyr * D_MODEL,
                                              xn_h, xn_l);                    // 3

        // in_proj: 2-term (Ah+Al)*Bh  (profiled control, launch #4)
        mma_gemm<2><<<dim3(2*D_INNER/128, M_ROWS/128, 1), 256, GSMEM(2)>>>(
            xn_h, xn_l,
            inpw_h + (long)lyr * 2*D_INNER*D_MODEL, nullptr,
            D_MODEL, D_MODEL, xr, 2*D_INNER, 2*D_INNER, nullptr, 0, 0);

        conv_silu_split_kernel<<<(M_ROWS*D_INNER/4 + 255)/256, 256>>>(
            xr, convw + lyr * D_INNER*D_CONV, convb + lyr * D_INNER,
            u, (__half2*)u_h, (__half2*)u_l);

        {
            int n4 = 128 * D_INNER / 4;
            split_pad_rows4<<<(n4 + 255)/256, 256>>>(
                xprojw + (long)lyr * XDBL_COLS * D_INNER, XDBL_COLS, D_INNER, 128,
                (__half2*)xpw_h, (__half2*)xpw_l);
        }
        mma_gemm<3><<<dim3(1, M_ROWS/128, 8), 256, GSMEM(3)>>>(
            u_h, u_l, xpw_h, xpw_l,
            D_INNER, D_INNER/8, part, 128, 128, nullptr, 0, (long)M_ROWS*128);
        reduce_xp_kernel<<<(M_ROWS*128 + 255)/256, 256>>>(part, xdbl, xdp_h, xdp_l);

        {
            int n4 = D_INNER * 64 / 4;
            split_pad_cols4<<<(n4 + 255)/256, 256>>>(
                dtpw + (long)lyr * D_INNER * DT_RANK, D_INNER, DT_RANK,
                DT_RANK, 64, (__half2*)dtw_h, (__half2*)dtw_l);
        }
        mma_gemm<3><<<dim3(D_INNER/128, M_ROWS/128, 1), 256, GSMEM(3)>>>(
            xdp_h, xdp_l, dtw_h, dtw_l,
            64, 64, delta, D_INNER, D_INNER, dtpb + lyr * D_INNER, 1, 0);

        scan_kernel<<<(BATCH*D_INNER)/32, 128>>>(
            delta, u, xdbl, xr, Alog + (long)lyr * D_INNER*D_STATE,
            Dw + lyr * D_INNER, y_h, y_l);

        if (lyr == 0)
            CVT4(outpw, N_LAYER * D_MODEL * D_INNER, outpw_h);

        // out_proj: 2-term, split-K=4
        mma_gemm<2><<<dim3(D_MODEL/128, M_ROWS/128, 4), 256, GSMEM(2)>>>(
            y_h, y_l,
            outpw_h + (long)lyr * D_MODEL*D_INNER, nullptr,
            D_INNER, D_INNER/4, part, D_MODEL, D_MODEL, nullptr, 0,
            (long)M_ROWS*D_MODEL);
        reduce_out_kernel<<<(M_ROWS*D_MODEL/4 + 255)/256, 256>>>(part, x);
    }

    CVT4(emb, VOCAB * D_MODEL, emb_h);
    rmsnorm_split_kernel<<<M_ROWS, 256>>>(x, normf, xn_h, xn_l);

    // logits: 1-term Ah*Bh
    mma_gemm<1><<<dim3(VOCAB/128, M_ROWS/128, 1), 256, GSMEM(1)>>>(
        xn_h, nullptr, emb_h, nullptr,
        D_MODEL, D_MODEL, out, VOCAB, VOCAB, nullptr, 0, 0);
}

// round 11
// speedup vs baseline: 1.3109x; 1.0137x over previous
#include <cuda_runtime.h>
#include <cuda_fp16.h>
#include <math.h>
#include <stdint.h>

// ---------------- model dims ----------------
#define BATCH      2
#define SEQ        1024
#define M_ROWS     (BATCH*SEQ)        // 2048
#define D_MODEL    768
#define D_INNER    1536
#define D_STATE    16
#define DT_RANK    48
#define D_CONV     4
#define XDBL_COLS  (DT_RANK + 2*D_STATE)   // 80
#define VOCAB      32000
#define N_LAYER    2
#define EPS        1e-5f

// ---------------- fp32 scratch ----------------
__device__ __align__(16) float g_x    [M_ROWS * D_MODEL];
__device__ __align__(16) float g_xr   [M_ROWS * 2 * D_INNER];
__device__ __align__(16) float g_u    [M_ROWS * D_INNER];
__device__ __align__(16) float g_xdbl [M_ROWS * XDBL_COLS];
__device__ __align__(16) float g_delta[M_ROWS * D_INNER];
__device__ __align__(16) float g_part [4 * M_ROWS * D_MODEL];

// ---------------- fp16 buffers ----------------
__device__ __align__(16) __half g_emb_h [VOCAB*D_MODEL];
__device__ __align__(16) __half g_inpw_h[N_LAYER*2*D_INNER*D_MODEL];
__device__ __align__(16) __half g_outpw_h[N_LAYER*D_MODEL*D_INNER];
__device__ __align__(16) __half g_xn_h[M_ROWS*D_MODEL];
__device__ __align__(16) __half g_xn_l[M_ROWS*D_MODEL];
__device__ __align__(16) __half g_u_h [M_ROWS*D_INNER];
__device__ __align__(16) __half g_u_l [M_ROWS*D_INNER];
__device__ __align__(16) __half g_y_h [M_ROWS*D_INNER];
__device__ __align__(16) __half g_y_l [M_ROWS*D_INNER];
__device__ __align__(16) __half g_xpw_h[128*D_INNER];
__device__ __align__(16) __half g_xpw_l[128*D_INNER];
__device__ __align__(16) __half g_dtw_h[D_INNER*64];
__device__ __align__(16) __half g_dtw_l[D_INNER*64];
__device__ __align__(16) __half g_xdp_h[M_ROWS*64];
__device__ __align__(16) __half g_xdp_l[M_ROWS*64];

// ================= helpers =================
__device__ __forceinline__ void split2(float v, __half& h, __half& l) {
    h = __float2half_rn(v);
    l = __float2half_rn(v - __half2float(h));
}

// ================= small kernels =================
__global__ void embed_kernel(const int* __restrict__ ids,
                             const float* __restrict__ emb,
                             float* __restrict__ x)
{
    int row = blockIdx.x;
    int tok = ids[row];
    const float4* src = (const float4*)(emb + (long)tok * D_MODEL);
    float4* dst = (float4*)(x + (long)row * D_MODEL);
    for (int i = threadIdx.x; i < D_MODEL/4; i += blockDim.x) dst[i] = src[i];
}

__global__ void rmsnorm_split_kernel(const float* __restrict__ x,
                                     const float* __restrict__ w,
                                     __half* __restrict__ oh,
                                     __half* __restrict__ ol)
{
    __shared__ float red[8];
    int row = blockIdx.x;
    const float* xp = x + (long)row * D_MODEL;
    float s = 0.f;
    for (int i = threadIdx.x; i < D_MODEL; i += 256) { float v = xp[i]; s += v*v; }
    #pragma unroll
    for (int o = 16; o; o >>= 1) s += __shfl_xor_sync(0xffffffffu, s, o);
    if ((threadIdx.x & 31) == 0) red[threadIdx.x >> 5] = s;
    __syncthreads();
    if (threadIdx.x < 8) {
        float t = red[threadIdx.x];
        #pragma unroll
        for (int o = 4; o; o >>= 1) t += __shfl_xor_sync(0xffu, t, o);
        if (threadIdx.x == 0) red[0] = t;
    }
    __syncthreads();
    float scale = rsqrtf(red[0] / (float)D_MODEL + EPS);
    for (int i = threadIdx.x; i < D_MODEL; i += 256) {
        float v = xp[i] * scale * w[i];
        __half h, l; split2(v, h, l);
        oh[(long)row * D_MODEL + i] = h;
        ol[(long)row * D_MODEL + i] = l;
    }
}

// fused: x += sum(4 split-K partials); rmsnorm(x)*w -> hi/lo split
__global__ void rms_res_split_kernel(float* __restrict__ x,
                                     const float* __restrict__ part,
                                     const float* __restrict__ w,
                                     __half* __restrict__ oh,
                                     __half* __restrict__ ol)
{
    __shared__ float red[8];
    __shared__ float vrow[D_MODEL];
    int row = blockIdx.x;
    float* xp = x + (long)row * D_MODEL;
    const long S = (long)M_ROWS * D_MODEL;
    float s = 0.f;
    for (int i = threadIdx.x; i < D_MODEL; i += 256) {
        float v = xp[i];
        long o = (long)row * D_MODEL + i;
        v += part[o] + part[S + o] + part[2*S + o] + part[3*S + o];
        vrow[i] = v;
        xp[i] = v;
        s += v * v;
    }
    #pragma unroll
    for (int o = 16; o; o >>= 1) s += __shfl_xor_sync(0xffffffffu, s, o);
    if ((threadIdx.x & 31) == 0) red[threadIdx.x >> 5] = s;
    __syncthreads();
    if (threadIdx.x < 8) {
        float t = red[threadIdx.x];
        #pragma unroll
        for (int o = 4; o; o >>= 1) t += __shfl_xor_sync(0xffu, t, o);
        if (threadIdx.x == 0) red[0] = t;
    }
    __syncthreads();
    float scale = rsqrtf(red[0] / (float)D_MODEL + EPS);
    for (int i = threadIdx.x; i < D_MODEL; i += 256) {
        float v = vrow[i] * scale * w[i];
        __half h, l; split2(v, h, l);
        oh[(long)row * D_MODEL + i] = h;
        ol[(long)row * D_MODEL + i] = l;
    }
}

// fp32 -> fp16 rn only, vec4 (for weight hi buffers)
__global__ void cvt4_kernel(const float4* __restrict__ s, int n4,
                            __half2* __restrict__ h)
{
    int i = blockIdx.x * blockDim.x + threadIdx.x;
    if (i >= n4) return;
    float4 v = s[i];
    h[2*i]   = __halves2half2(__float2half_rn(v.x), __float2half_rn(v.y));
    h[2*i+1] = __halves2half2(__float2half_rn(v.z), __float2half_rn(v.w));
}

__global__ void split_pad_rows4(const float* __restrict__ s, int rows_real, int K,
                                int rows_pad,
                                __half2* __restrict__ h, __half2* __restrict__ l)
{
    int i = blockIdx.x * blockDim.x + threadIdx.x;
    int n4 = rows_pad * K / 4;
    if (i >= n4) return;
    int r = (i*4) / K;
    float4 v = (r < rows_real) ? *(const float4*)(s + (long)(i*4))
                               : make_float4(0,0,0,0);
    __half hx,lx,hy,ly,hz,lz,hw,lw;
    split2(v.x,hx,lx); split2(v.y,hy,ly); split2(v.z,hz,lz); split2(v.w,hw,lw);
    h[2*i]   = __halves2half2(hx,hy);
    h[2*i+1] = __halves2half2(hz,hw);
    l[2*i]   = __halves2half2(lx,ly);
    l[2*i+1] = __halves2half2(lz,lw);
}

__global__ void split_pad_cols4(const float* __restrict__ s, int rows, int src_ld,
                                int k_take, int k_pad,
                                __half2* __restrict__ h, __half2* __restrict__ l)
{
    int i = blockIdx.x * blockDim.x + threadIdx.x;
    int n4 = rows * k_pad / 4;
    if (i >= n4) return;
    int kp4 = k_pad / 4;
    int r = i / kp4, k = (i % kp4) * 4;
    float4 v = (k < k_take) ? *(const float4*)(s + (long)r * src_ld + k)
                            : make_float4(0,0,0,0);
    __half hx,lx,hy,ly,hz,lz,hw,lw;
    split2(v.x,hx,lx); split2(v.y,hy,ly); split2(v.z,hz,lz); split2(v.w,hw,lw);
    h[2*i]   = __halves2half2(hx,hy);
    h[2*i+1] = __halves2half2(hz,hw);
    l[2*i]   = __halves2half2(lx,ly);
    l[2*i+1] = __halves2half2(lz,lw);
}

__global__ void conv_silu_split_kernel(const float* __restrict__ xr,
                                       const float* __restrict__ cw,
                                       const float* __restrict__ cb,
                                       float* __restrict__ u,
                                       __half2* __restrict__ uh,
                                       __half2* __restrict__ ul)
{
    int i = blockIdx.x * blockDim.x + threadIdx.x;
    if (i >= M_ROWS * D_INNER / 4) return;
    int c = (i*4) % D_INNER;
    int m = (i*4) / D_INNER;
    int l = m % SEQ;
    const float* base = xr + (long)m * (2*D_INNER) + c;
    float4 v0  = *(const float4*)base;
    float4 vm1 = (l >= 1) ? *(const float4*)(base - 1*(2*D_INNER)) : make_float4(0,0,0,0);
    float4 vm2 = (l >= 2) ? *(const float4*)(base - 2*(2*D_INNER)) : make_float4(0,0,0,0);
    float4 vm3 = (l >= 3) ? *(const float4*)(base - 3*(2*D_INNER)) : make_float4(0,0,0,0);
    float4 cbv = *(const float4*)(cb + c);
    const float* p0 = &v0.x; const float* p1 = &vm1.x;
    const float* p2 = &vm2.x; const float* p3 = &vm3.x;
    const float* pb = &cbv.x;
    float o[4];
    #pragma unroll
    for (int t = 0; t < 4; t++) {
        float4 w = *(const float4*)(cw + (c + t) * 4);
        float acc = pb[t] + w.w * p0[t] + w.z * p1[t] + w.y * p2[t] + w.x * p3[t];
        o[t] = acc / (1.f + __expf(-acc));
    }
    *(float4*)(u + (long)i*4) = make_float4(o[0], o[1], o[2], o[3]);
    __half hx,lx,hy,ly,hz,lz,hw,lw;
    split2(o[0],hx,lx); split2(o[1],hy,ly); split2(o[2],hz,lz); split2(o[3],hw,lw);
    uh[2*i]   = __halves2half2(hx,hy);
    uh[2*i+1] = __halves2half2(hz,hw);
    ul[2*i]   = __halves2half2(lx,ly);
    ul[2*i+1] = __halves2half2(lz,lw);
}

__global__ void reduce_xp_kernel(const float* __restrict__ p,
                                 float* __restrict__ xdbl,
                                 __half* __restrict__ xdph,
                                 __half* __restrict__ xdpl)
{
    int i = blockIdx.x * blockDim.x + threadIdx.x;
    if (i >= M_ROWS * 128) return;
    int r = i >> 7, c = i & 127;
    const long S = (long)M_ROWS * 128;
    float s = 0.f;
    #pragma unroll
    for (int z = 0; z < 8; z++) s += p[z*S + i];
    if (c < XDBL_COLS) xdbl[(long)r * XDBL_COLS + c] = s;
    if (c < 64) {
        float v = (c < DT_RANK) ? s : 0.f;
        __half h, l; split2(v, h, l);
        xdph[(long)r*64 + c] = h;
        xdpl[(long)r*64 + c] = l;
    }
}

// selective scan: 4 states per lane (quad per channel), 2-shfl reduce,
// float4 B/C loads, software-pipelined; D skip + silu gate + fp16 split.
// blockDim 64 -> 16 channels/block; grid = 3072/16 = 192 (covers all SMs).
__global__ void scan_kernel(const float* __restrict__ delta,
                            const float* __restrict__ u,
                            const float* __restrict__ xdbl,
                            const float* __restrict__ xr,
                            const float* __restrict__ A_log,
                            const float* __restrict__ Dp,
                            __half* __restrict__ yh,
                            __half* __restrict__ yl)
{
    int gid = blockIdx.x * (blockDim.x / 4) + (threadIdx.x >> 2);
    int q   = threadIdx.x & 3;
    if (gid >= BATCH * D_INNER) return;
    int b  = gid / D_INNER;
    int di = gid % D_INNER;

    float An0 = -__expf(A_log[di * D_STATE + q*4 + 0]);
    float An1 = -__expf(A_log[di * D_STATE + q*4 + 1]);
    float An2 = -__expf(A_log[di * D_STATE + q*4 + 2]);
    float An3 = -__expf(A_log[di * D_STATE + q*4 + 3]);
    float Dv = Dp[di];
    float h0 = 0.f, h1 = 0.f, h2 = 0.f, h3 = 0.f;

    long m0 = (long)b * SEQ;
    const float* dptr = delta + m0 * D_INNER + di;
    const float* uptr = u     + m0 * D_INNER + di;
    const float* rptr = xr    + m0 * (2*D_INNER) + D_INNER + di;
    const float* bptr = xdbl  + m0 * XDBL_COLS + DT_RANK + q*4;
    const float* cptr = xdbl  + m0 * XDBL_COLS + DT_RANK + D_STATE + q*4;
    __half* yhp = yh + m0 * D_INNER + di;
    __half* ylp = yl + m0 * D_INNER + di;

    float dv = dptr[0], uv = uptr[0], rv = rptr[0];
    float4 Bv = *(const float4*)bptr;
    float4 Cv = *(const float4*)cptr;

    for (int l = 0; l < SEQ; l++) {
        float dv_n = 0.f, uv_n = 0.f, rv_n = 0.f;
        float4 Bv_n = make_float4(0,0,0,0), Cv_n = Bv_n;
        if (l + 1 < SEQ) {
            long ln = l + 1;
            dv_n = dptr[ln * D_INNER];
            uv_n = uptr[ln * D_INNER];
            rv_n = rptr[ln * (2*D_INNER)];
            Bv_n = *(const float4*)(bptr + ln * XDBL_COLS);
            Cv_n = *(const float4*)(cptr + ln * XDBL_COLS);
        }

        float du = dv * uv;
        h0 = fmaf(__expf(dv * An0), h0, du * Bv.x);
        h1 = fmaf(__expf(dv * An1), h1, du * Bv.y);
        h2 = fmaf(__expf(dv * An2), h2, du * Bv.z);
        h3 = fmaf(__expf(dv * An3), h3, du * Bv.w);
        float p = fmaf(h0, Cv.x, h1 * Cv.y) + fmaf(h2, Cv.z, h3 * Cv.w);
        p += __shfl_xor_sync(0xffffffffu, p, 2);
        p += __shfl_xor_sync(0xffffffffu, p, 1);
        if (q == 0) {
            float yv = (p + uv * Dv) * (rv / (1.f + __expf(-rv)));
            __half hb, lb; split2(yv, hb, lb);
            yhp[(long)l * D_INNER] = hb;
            ylp[(long)l * D_INNER] = lb;
        }
        dv = dv_n; uv = uv_n; rv = rv_n; Bv = Bv_n; Cv = Cv_n;
    }
}

// ================= mma.sync split-fp16 GEMM =================
// 128x128x32 tiles, 8 warps (2Mx4N), ldmatrix.x4 A+B.
// TERMS=3: 2-stage double-sync; TERMS<=2: 3-stage single-sync.
// SWAP=1: blockIdx.x indexes M (M-fastest rasterization for B-tile L2 reuse).
// mode 0: plain (C += z*zstride)   mode 1: softplus(acc + ext[col])
#define GPITCH 40

__device__ __forceinline__ uint32_t smem_u32(const void* p) {
    uint32_t a;
    asm("{ .reg .u64 t; cvta.to.shared.u64 t, %1; cvt.u32.u64 %0, t; }" : "=r"(a) : "l"(p));
    return a;
}

#define LDSM_X4(r, addr) \
    asm volatile("ldmatrix.sync.aligned.m8n8.x4.shared.b16 {%0,%1,%2,%3}, [%4];" \
        : "=r"((r)[0]),"=r"((r)[1]),"=r"((r)[2]),"=r"((r)[3]) : "r"(addr))

#define MMA_F16(c, a, b) \
    asm volatile("mma.sync.aligned.m16n8k16.row.col.f32.f16.f16.f32 " \
        "{%0,%1,%2,%3},{%4,%5,%6,%7},{%8,%9},{%0,%1,%2,%3};" \
        : "+f"((c)[0]),"+f"((c)[1]),"+f"((c)[2]),"+f"((c)[3]) \
        : "r"((a)[0]),"r"((a)[1]),"r"((a)[2]),"r"((a)[3]),"r"((b)[0]),"r"((b)[1]))

#define CP16(dst, src) \
    asm volatile("cp.async.cg.shared.global [%0], [%1], 16;" :: "r"(dst), "l"(src))
#define CP_COMMIT() asm volatile("cp.async.commit_group;" ::: "memory")
#define CP_WAIT(n)  asm volatile("cp.async.wait_group %0;" :: "n"(n) : "memory")

template<int TERMS, int SWAP>
__global__ void __launch_bounds__(256, 2) mma_gemm(
    const __half* __restrict__ Ah, const __half* __restrict__ Al,
    const __half* __restrict__ Bh, const __half* __restrict__ Bl,
    int lda, int klen,
    float* __restrict__ C, int ldc, int Nreal,
    const float* __restrict__ ext, int mode, long zstride)
{
    constexpr int AROWS = (TERMS == 1) ? 128 : 256;
    constexpr int ROWS  = AROWS + ((TERMS == 3) ? 256 : 128);
    constexpr int SELEM = ROWS * GPITCH;
    constexpr int NS    = (TERMS == 3) ? 2 : 3;
    constexpr int LITER = ROWS / 64;

    extern __shared__ __half sm[];
    const uint32_t sbase = smem_u32(sm);
    const int tid  = threadIdx.x;
    const int lane = tid & 31;
    const int w    = tid >> 5;
    const int wm   = (w >> 2) << 6;
    const int wn   = (w & 3) << 5;
    const long bm  = (long)(SWAP ? blockIdx.x : blockIdx.y) * 128;
    const long bn  = (long)(SWAP ? blockIdx.y : blockIdx.x) * 128;
    const int koff = blockIdx.z * klen;
    C += (long)blockIdx.z * zstride;

    float acc[4][4][4];
    #pragma unroll
    for (int i = 0; i < 4; i++)
        #pragma unroll
        for (int j = 0; j < 4; j++)
            #pragma unroll
            for (int e = 0; e < 4; e++) acc[i][j][e] = 0.f;

    const int NC = klen >> 5;

    #define LOAD_STAGE(st, kc) do {                                           \
        int _k0 = koff + ((kc) << 5);                                         \
        _Pragma("unroll")                                                     \
        for (int _it = 0; _it < LITER; _it++) {                               \
            int _i = _it * 256 + tid;                                         \
            int _rg = _i >> 2, _ch = _i & 3;                                  \
            const __half* _gb; long _grow;                                    \
            if (_rg < 128)                    { _gb = Ah; _grow = bm + _rg; } \
            else if (TERMS >= 2 && _rg < 256) { _gb = Al; _grow = bm + _rg - 128; } \
            else if (_rg < AROWS + 128)       { _gb = Bh; _grow = bn + _rg - AROWS; } \
            else                              { _gb = Bl; _grow = bn + _rg - AROWS - 128; } \
            const void* _src = _gb + _grow * (long)lda + _k0 + _ch * 8;       \
            uint32_t _dst = sbase + ((st) * SELEM + _rg * GPITCH              \
                                     + _ch * 8) * 2;                          \
            CP16(_dst, _src);                                                 \
        }                                                                     \
        CP_COMMIT();                                                          \
    } while (0)

    #define MMA_BODY(stg) do {                                                \
        const uint32_t aH = (stg);                                            \
        const uint32_t aL = (stg) + (128 * GPITCH) * 2;                       \
        const uint32_t bH = (stg) + (AROWS * GPITCH) * 2;                     \
        const uint32_t bL = bH + (128 * GPITCH) * 2;                          \
        _Pragma("unroll")                                                     \
        for (int ks = 0; ks < 2; ks++) {                                      \
            const int k0 = ks << 4;                                           \
            const uint32_t aoff = ((wm + (lane & 15)) * GPITCH                \
                                   + k0 + ((lane >> 4) << 3)) * 2;            \
            const int brow = wn + (lane & 7) + ((lane >> 4) << 3);            \
            const uint32_t boff = (brow * GPITCH + k0                         \
                                   + (((lane >> 3) & 1) << 3)) * 2;           \
            uint32_t ah[4][4];                                                \
            uint32_t bhf[2][4];                                               \
            _Pragma("unroll")                                                 \
            for (int mi = 0; mi < 4; mi++)                                    \
                LDSM_X4(ah[mi], aH + aoff + mi * 16 * GPITCH * 2);            \
            LDSM_X4(bhf[0], bH + boff);                                       \
            LDSM_X4(bhf[1], bH + boff + 16 * GPITCH * 2);                     \
            _Pragma("unroll")                                                 \
            for (int mi = 0; mi < 4; mi++)                                    \
                _Pragma("unroll")                                             \
                for (int ni = 0; ni < 4; ni++)                                \
                    MMA_F16(acc[mi][ni], ah[mi], &bhf[ni>>1][(ni&1)<<1]);     \
            if (TERMS == 3) {                                                 \
                uint32_t blf[2][4];                                           \
                LDSM_X4(blf[0], bL + boff);                                   \
                LDSM_X4(blf[1], bL + boff + 16 * GPITCH * 2);                 \
                _Pragma("unroll")                                             \
                for (int mi = 0; mi < 4; mi++)                                \
                    _Pragma("unroll")                                         \
                    for (int ni = 0; ni < 4; ni++)                            \
                        MMA_F16(acc[mi][ni], ah[mi], &blf[ni>>1][(ni&1)<<1]); \
            }                                                                 \
            if (TERMS >= 2) {                                                 \
                uint32_t al[4][4];                                            \
                _Pragma("unroll")                                             \
                for (int mi = 0; mi < 4; mi++)                                \
                    LDSM_X4(al[mi], aL + aoff + mi * 16 * GPITCH * 2);        \
                _Pragma("unroll")                                             \
                for (int mi = 0; mi < 4; mi++)                                \
                    _Pragma("unroll")                                         \
                    for (int ni = 0; ni < 4; ni++)                            \
                        MMA_F16(acc[mi][ni], al[mi], &bhf[ni>>1][(ni&1)<<1]); \
            }                                                                 \
        }                                                                     \
    } while (0)

    LOAD_STAGE(0, 0);
    if (NC > 1) LOAD_STAGE(1, 1);

    if (NS == 2) {
        for (int c = 0; c < NC; c++) {
            if (c + 1 < NC) CP_WAIT(1);
            else            CP_WAIT(0);
            __syncthreads();
            MMA_BODY(sbase + ((c & 1) * SELEM) * 2);
            __syncthreads();
            if (c + 2 < NC) LOAD_STAGE(c & 1, c + 2);
        }
    } else {
        for (int c = 0; c < NC; c++) {
            if (c + 1 < NC) CP_WAIT(1);
            else            CP_WAIT(0);
            __syncthreads();
            if (c + 2 < NC) LOAD_STAGE((c + 2) % 3, c + 2);
            MMA_BODY(sbase + ((c % 3) * SELEM) * 2);
        }
    }
    #undef LOAD_STAGE
    #undef MMA_BODY

    // ---- epilogue ----
    const int g  = lane >> 2;
    const int cc = (lane & 3) << 1;
    #pragma unroll
    for (int mi = 0; mi < 4; mi++) {
        #pragma unroll
        for (int ni = 0; ni < 4; ni++) {
            int col = (int)bn + wn + ni * 8 + cc;
            if (col >= Nreal) continue;
            long row0 = bm + wm + mi * 16 + g;
            float v0 = acc[mi][ni][0], v1 = acc[mi][ni][1];
            float v2 = acc[mi][ni][2], v3 = acc[mi][ni][3];
            if (mode == 1) {
                float b0 = ext[col], b1 = ext[col + 1];
                v0 += b0; v1 += b1; v2 += b0; v3 += b1;
                v0 = (v0 > 20.f) ? v0 : log1pf(__expf(v0));
                v1 = (v1 > 20.f) ? v1 : log1pf(__expf(v1));
                v2 = (v2 > 20.f) ? v2 : log1pf(__expf(v2));
                v3 = (v3 > 20.f) ? v3 : log1pf(__expf(v3));
            }
            *(float2*)(C + row0 * ldc + col)       = make_float2(v0, v1);
            *(float2*)(C + (row0 + 8) * ldc + col) = make_float2(v2, v3);
        }
    }
}

#define GSMEM(TERMS) \
    ((((TERMS)==3) ? 2*512 : ((TERMS)==2) ? 3*384 : 3*256) * GPITCH * 2)

// ================= launch =================
extern "C" void kernel_launch(void* const* d_in, const int* in_sizes, int n_in,
                              void* d_out, int out_size)
{
    const int*   ids    = (const int*)  d_in[0];
    const float* emb    = (const float*)d_in[1];
    const float* normw  = (const float*)d_in[2];
    const float* inpw   = (const float*)d_in[3];
    const float* convw  = (const float*)d_in[4];
    const float* convb  = (const float*)d_in[5];
    const float* xprojw = (const float*)d_in[6];
    const float* dtpw   = (const float*)d_in[7];
    const float* dtpb   = (const float*)d_in[8];
    const float* Alog   = (const float*)d_in[9];
    const float* Dw     = (const float*)d_in[10];
    const float* outpw  = (const float*)d_in[11];
    const float* normf  = (const float*)d_in[12];
    float* out = (float*)d_out;

    float *x, *xr, *u, *xdbl, *delta, *part;
    cudaGetSymbolAddress((void**)&x,     g_x);
    cudaGetSymbolAddress((void**)&xr,    g_xr);
    cudaGetSymbolAddress((void**)&u,     g_u);
    cudaGetSymbolAddress((void**)&xdbl,  g_xdbl);
    cudaGetSymbolAddress((void**)&delta, g_delta);
    cudaGetSymbolAddress((void**)&part,  g_part);

    __half *emb_h, *inpw_h, *outpw_h;
    __half *xn_h, *xn_l, *u_h, *u_l, *y_h, *y_l;
    __half *xpw_h, *xpw_l, *dtw_h, *dtw_l, *xdp_h, *xdp_l;
    cudaGetSymbolAddress((void**)&emb_h,  g_emb_h);
    cudaGetSymbolAddress((void**)&inpw_h, g_inpw_h);
    cudaGetSymbolAddress((void**)&outpw_h,g_outpw_h);
    cudaGetSymbolAddress((void**)&xn_h,   g_xn_h);    cudaGetSymbolAddress((void**)&xn_l,   g_xn_l);
    cudaGetSymbolAddress((void**)&u_h,    g_u_h);     cudaGetSymbolAddress((void**)&u_l,    g_u_l);
    cudaGetSymbolAddress((void**)&y_h,    g_y_h);     cudaGetSymbolAddress((void**)&y_l,    g_y_l);
    cudaGetSymbolAddress((void**)&xpw_h,  g_xpw_h);   cudaGetSymbolAddress((void**)&xpw_l,  g_xpw_l);
    cudaGetSymbolAddress((void**)&dtw_h,  g_dtw_h);   cudaGetSymbolAddress((void**)&dtw_l,  g_dtw_l);
    cudaGetSymbolAddress((void**)&xdp_h,  g_xdp_h);   cudaGetSymbolAddress((void**)&xdp_l,  g_xdp_l);

    cudaFuncSetAttribute((const void*)mma_gemm<3,0>,
                         cudaFuncAttributeMaxDynamicSharedMemorySize, GSMEM(3));
    cudaFuncSetAttribute((const void*)mma_gemm<2,0>,
                         cudaFuncAttributeMaxDynamicSharedMemorySize, GSMEM(2));
    cudaFuncSetAttribute((const void*)mma_gemm<1,1>,
                         cudaFuncAttributeMaxDynamicSharedMemorySize, GSMEM(1));

    #define CVT4(src, n, h) \
        cvt4_kernel<<<((n)/4 + 255) / 256, 256>>>((const float4*)(src), (n)/4, \
            (__half2*)(h))

    embed_kernel<<<M_ROWS, 256>>>(ids, emb, x);                               // 1
    CVT4(inpw, N_LAYER * 2 * D_INNER * D_MODEL, inpw_h);                      // 2

    for (int lyr = 0; lyr < N_LAYER; lyr++) {
        if (lyr == 0)
            rmsnorm_split_kernel<<<M_ROWS, 256>>>(x, normw, xn_h, xn_l);      // 3
        // (lyr==1: xn_h/xn_l already produced by rms_res_split below)

        // in_proj: 2-term (Ah+Al)*Bh  (profiled control, launch #4)
        mma_gemm<2,0><<<dim3(2*D_INNER/128, M_ROWS/128, 1), 256, GSMEM(2)>>>(
            xn_h, xn_l,
            inpw_h + (long)lyr * 2*D_INNER*D_MODEL, nullptr,
            D_MODEL, D_MODEL, xr, 2*D_INNER, 2*D_INNER, nullptr, 0, 0);

        conv_silu_split_kernel<<<(M_ROWS*D_INNER/4 + 255)/256, 256>>>(
            xr, convw + lyr * D_INNER*D_CONV, convb + lyr * D_INNER,
            u, (__half2*)u_h, (__half2*)u_l);

        {
            int n4 = 128 * D_INNER / 4;
            split_pad_rows4<<<(n4 + 255)/256, 256>>>(
                xprojw + (long)lyr * XDBL_COLS * D_INNER, XDBL_COLS, D_INNER, 128,
                (__half2*)xpw_h, (__half2*)xpw_l);
        }
        mma_gemm<3,0><<<dim3(1, M_ROWS/128, 8), 256, GSMEM(3)>>>(
            u_h, u_l, xpw_h, xpw_l,
            D_INNER, D_INNER/8, part, 128, 128, nullptr, 0, (long)M_ROWS*128);
        reduce_xp_kernel<<<(M_ROWS*128 + 255)/256, 256>>>(part, xdbl, xdp_h, xdp_l);

        {
            int n4 = D_INNER * 64 / 4;
            split_pad_cols4<<<(n4 + 255)/256, 256>>>(
                dtpw + (long)lyr * D_INNER * DT_RANK, D_INNER, DT_RANK,
                DT_RANK, 64, (__half2*)dtw_h, (__half2*)dtw_l);
        }
        mma_gemm<3,0><<<dim3(D_INNER/128, M_ROWS/128, 1), 256, GSMEM(3)>>>(
            xdp_h, xdp_l, dtw_h, dtw_l,
            64, 64, delta, D_INNER, D_INNER, dtpb + lyr * D_INNER, 1, 0);

        scan_kernel<<<(BATCH*D_INNER)/16, 64>>>(
            delta, u, xdbl, xr, Alog + (long)lyr * D_INNER*D_STATE,
            Dw + lyr * D_INNER, y_h, y_l);

        if (lyr == 0)
            CVT4(outpw, N_LAYER * D_MODEL * D_INNER, outpw_h);

        // out_proj: 2-term, split-K=4 -> partials
        mma_gemm<2,0><<<dim3(D_MODEL/128, M_ROWS/128, 4), 256, GSMEM(2)>>>(
            y_h, y_l,
            outpw_h + (long)lyr * D_MODEL*D_INNER, nullptr,
            D_INNER, D_INNER/4, part, D_MODEL, D_MODEL, nullptr, 0,
            (long)M_ROWS*D_MODEL);

        // fused residual-reduce + rmsnorm + split for the NEXT stage
        const float* nw = (lyr == 0) ? (normw + D_MODEL) : normf;
        rms_res_split_kernel<<<M_ROWS, 256>>>(x, part, nw, xn_h, xn_l);
    }

    CVT4(emb, VOCAB * D_MODEL, emb_h);

    // logits: 1-term Ah*Bh, M-fastest rasterization (SWAP=1) for B L2 reuse
    mma_gemm<1,1><<<dim3(M_ROWS/128, VOCAB/128, 1), 256, GSMEM(1)>>>(
        xn_h, nullptr, emb_h, nullptr,
        D_MODEL, D_MODEL, out, VOCAB, VOCAB, nullptr, 0, 0);
}